// round 14
// baseline (speedup 1.0000x reference)
#include <cuda_runtime.h>
#include <cuda_bf16.h>
#include <stdint.h>

// ---------------------------------------------------------------------------
// MultiHeadSelfAttention: B=2, S=2048, D=1024, H=16, dk=64
// R13: fused attention split into pass1/pass2 kernels, each K-split x2
//      (2048 CTAs -> ~7 waves, kills the 15% 3.46-wave tail). Partial ctx
//      merged + exactly normalized by a small merge kernel. Precision path
//      identical to R12 (2-mma pass1, 3-term pass2, exact ctx norm).
// ---------------------------------------------------------------------------

namespace {
constexpr int BATCH = 2, S = 2048, D = 1024, H = 16, DK = 64, BH = 32;
constexpr long long OUT_ELEMS = (long long)BATCH * S * D;          // 4,194,304
constexpr long long ATT_ELEMS = (long long)BH * S * (long long)S;  // 134,217,728
constexpr int QST = 72;     // attn: Q smem stride (hi plane) bf16
constexpr int KST = 136;    // attn: K/V smem stride bf16
constexpr int GST = 40;     // gemm smem stride bf16
constexpr int NSTG = 5;     // gemm cp.async stages
constexpr int GSMEM = NSTG * 128 * GST * 2 * 2;            // 102400 B
constexpr int ASMEM = (64 * QST + 3 * 128 * KST) * 2;      // 113664 B
}

// ---- scratch (allocation-free __device__ globals) ----
__device__ __nv_bfloat16 g_xqh[(size_t)BATCH * S * D], g_xql[(size_t)BATCH * S * D];
__device__ __nv_bfloat16 g_xkh[(size_t)BATCH * S * D], g_xkl[(size_t)BATCH * S * D];
__device__ __nv_bfloat16 g_xvh[(size_t)BATCH * S * D], g_xvl[(size_t)BATCH * S * D];
__device__ __nv_bfloat16 g_wqh[(size_t)D * D], g_wql[(size_t)D * D];
__device__ __nv_bfloat16 g_wkh[(size_t)D * D], g_wkl[(size_t)D * D];
__device__ __nv_bfloat16 g_wvh[(size_t)D * D], g_wvl[(size_t)D * D];
__device__ __nv_bfloat16 g_woh[(size_t)D * D], g_wol[(size_t)D * D];
__device__ __nv_bfloat16 g_cxh[(size_t)BATCH * S * D], g_cxl[(size_t)BATCH * S * D];
__device__ __nv_bfloat16 g_qh[(size_t)BH * S * DK], g_ql[(size_t)BH * S * DK];
__device__ __nv_bfloat16 g_kh[(size_t)BH * S * DK], g_kl[(size_t)BH * S * DK];
__device__ __nv_bfloat16 g_vh[(size_t)BH * S * DK], g_vl[(size_t)BH * S * DK];
__device__ float g_rs[(size_t)BH * S];     // pass1 rowsums
__device__ float g_rs2[(size_t)BH * S];    // exact sums of written P
__device__ float g_ct0[(size_t)BATCH * S * D];   // partial ctx, kslice 0
__device__ float g_ct1[(size_t)BATCH * S * D];   // partial ctx, kslice 1

// ------------------------------ PTX helpers --------------------------------
__device__ __forceinline__ uint32_t smaddr(const void* p) {
    return (uint32_t)__cvta_generic_to_shared(p);
}
__device__ __forceinline__ void ldsm4(uint32_t& r0, uint32_t& r1, uint32_t& r2,
                                      uint32_t& r3, uint32_t a) {
    asm volatile("ldmatrix.sync.aligned.m8n8.x4.shared.b16 {%0,%1,%2,%3}, [%4];"
                 : "=r"(r0), "=r"(r1), "=r"(r2), "=r"(r3) : "r"(a));
}
__device__ __forceinline__ void ldsm4t(uint32_t& r0, uint32_t& r1, uint32_t& r2,
                                       uint32_t& r3, uint32_t a) {
    asm volatile("ldmatrix.sync.aligned.m8n8.x4.trans.shared.b16 {%0,%1,%2,%3}, [%4];"
                 : "=r"(r0), "=r"(r1), "=r"(r2), "=r"(r3) : "r"(a));
}
__device__ __forceinline__ void mma16816(float* c, const uint32_t* a,
                                         uint32_t b0, uint32_t b1) {
    asm volatile("mma.sync.aligned.m16n8k16.row.col.f32.bf16.bf16.f32 "
                 "{%0,%1,%2,%3}, {%4,%5,%6,%7}, {%8,%9}, {%0,%1,%2,%3};"
                 : "+f"(c[0]), "+f"(c[1]), "+f"(c[2]), "+f"(c[3])
                 : "r"(a[0]), "r"(a[1]), "r"(a[2]), "r"(a[3]), "r"(b0), "r"(b1));
}
__device__ __forceinline__ uint32_t packbf(float a, float b) {
    __nv_bfloat162 t = __halves2bfloat162(__float2bfloat16(a), __float2bfloat16(b));
    return *reinterpret_cast<uint32_t*>(&t);
}
__device__ __forceinline__ void cpa16(uint32_t dst, const void* src) {
    asm volatile("cp.async.cg.shared.global [%0], [%1], 16;" :: "r"(dst), "l"(src));
}
#define CP_COMMIT() asm volatile("cp.async.commit_group;")
#define CP_WAIT(N)  asm volatile("cp.async.wait_group %0;" :: "n"(N))

__device__ __forceinline__ void split4(const float4 f, uint2& hi, uint2& lo) {
    __nv_bfloat16 hx = __float2bfloat16(f.x), hy = __float2bfloat16(f.y);
    __nv_bfloat16 hz = __float2bfloat16(f.z), hw = __float2bfloat16(f.w);
    __nv_bfloat16 lx = __float2bfloat16(f.x - __bfloat162float(hx));
    __nv_bfloat16 ly = __float2bfloat16(f.y - __bfloat162float(hy));
    __nv_bfloat16 lz = __float2bfloat16(f.z - __bfloat162float(hz));
    __nv_bfloat16 lw = __float2bfloat16(f.w - __bfloat162float(hw));
    __nv_bfloat162 h01 = __halves2bfloat162(hx, hy), h23 = __halves2bfloat162(hz, hw);
    __nv_bfloat162 l01 = __halves2bfloat162(lx, ly), l23 = __halves2bfloat162(lz, lw);
    hi.x = *reinterpret_cast<uint32_t*>(&h01); hi.y = *reinterpret_cast<uint32_t*>(&h23);
    lo.x = *reinterpret_cast<uint32_t*>(&l01); lo.y = *reinterpret_cast<uint32_t*>(&l23);
}

// ---------------------------------------------------------------------------
// zero rowsum arrays (graph-replayed every launch)
// ---------------------------------------------------------------------------
__global__ void __launch_bounds__(256)
zero_rs(float* __restrict__ rs, float* __restrict__ rs2)
{
    const int i = blockIdx.x * 256 + threadIdx.x;
    if (i < BH * S) { rs[i] = 0.0f; rs2[i] = 0.0f; }
}

// ---------------------------------------------------------------------------
// Elementwise fp32 -> bf16 hi/lo plane split. grid.z selects tensor.
// ---------------------------------------------------------------------------
struct ConvArgs {
    const float* src[8];
    __nv_bfloat16* hi[8];
    __nv_bfloat16* lo[8];
    int n4[8];
};

__global__ void __launch_bounds__(256)
convert_split(ConvArgs a)
{
    const int z = blockIdx.z;
    const int idx = blockIdx.x * 256 + threadIdx.x;
    if (idx >= a.n4[z]) return;
    float4 f = ((const float4*)a.src[z])[idx];
    uint2 hi, lo;
    split4(f, hi, lo);
    ((uint2*)a.hi[z])[idx] = hi;
    ((uint2*)a.lo[z])[idx] = lo;
}

// ---------------------------------------------------------------------------
// merge partial ctx: o = (c0 + c1) / rs2[row]; emit bf16 hi/lo planes.
// One block per token row (256 thr x float4 = 1024 cols).
// ---------------------------------------------------------------------------
__global__ void __launch_bounds__(256)
merge_ctx(const float* __restrict__ c0, const float* __restrict__ c1,
          const float* __restrict__ rs2,
          __nv_bfloat16* __restrict__ cxh, __nv_bfloat16* __restrict__ cxl)
{
    const int idx = blockIdx.x * 256 + threadIdx.x;   // float4 index
    const int row = idx >> 8;                         // D/4 = 256 per row
    const int col4 = idx & 255, head = col4 >> 4;
    const int s = row & (S - 1), bz = row >> 11;
    const float inv = 1.0f / rs2[((size_t)(bz * H + head)) * S + s];
    float4 a = ((const float4*)c0)[idx];
    float4 b = ((const float4*)c1)[idx];
    float4 o = make_float4((a.x + b.x) * inv, (a.y + b.y) * inv,
                           (a.z + b.z) * inv, (a.w + b.w) * inv);
    uint2 hi, lo;
    split4(o, hi, lo);
    ((uint2*)cxh)[idx] = hi;
    ((uint2*)cxl)[idx] = lo;
}

// ---------------------------------------------------------------------------
// Dense NT GEMM (R12, measured 109 us/unit). 128x128 CTA, BK=16, NSTG=5.
// ---------------------------------------------------------------------------
struct GemmArgs {
    const __nv_bfloat16 *ah[3], *al[3], *bh[3], *bl[3];
    float* c;
    __nv_bfloat16 *chi[3], *clo[3];
};

template <int EPI>
__global__ void __launch_bounds__(256, 2)
gemm_bf16(GemmArgs ga)
{
    constexpr int K = 1024;
    extern __shared__ __align__(16) __nv_bfloat16 sm[];
    __nv_bfloat16* As = sm;
    __nv_bfloat16* Bs = sm + NSTG * 128 * GST;

    const int zi = blockIdx.z;
    const __nv_bfloat16* Ah = ga.ah[zi];
    const __nv_bfloat16* Al = ga.al[zi];
    const __nv_bfloat16* Bh = ga.bh[zi];
    const __nv_bfloat16* Bl = ga.bl[zi];

    const int tid = threadIdx.x, w = tid >> 5, l = tid & 31;
    const int m0 = blockIdx.y * 128, n0 = blockIdx.x * 128;
    const int wm = (w >> 2) * 64, wn = (w & 3) * 32;

    const int lrow = tid & 127, lpl = tid >> 7;
    const __nv_bfloat16* srcA = (lpl ? Al : Ah) + (size_t)(m0 + lrow) * K;
    const __nv_bfloat16* srcB = (lpl ? Bl : Bh) + (size_t)(n0 + lrow) * K;

    auto issue = [&](int kt, int stg) {
        const uint32_t da = smaddr(As + (stg * 128 + lrow) * GST + lpl * 16);
        const __nv_bfloat16* sa = srcA + kt * 16;
        cpa16(da, sa); cpa16(da + 16, sa + 8);
        const uint32_t db = smaddr(Bs + (stg * 128 + lrow) * GST + lpl * 16);
        const __nv_bfloat16* sb = srcB + kt * 16;
        cpa16(db, sb); cpa16(db + 16, sb + 8);
        CP_COMMIT();
    };

    const int afr = wm + (l & 15);
    const int afc = (l >> 4) * 8;
    const int bg  = l >> 3;
    const int bfr = wn + ((bg >> 1) << 3) + (l & 7);
    const int bfc = (bg & 1) * 8;

    issue(0, 0); issue(1, 1); issue(2, 2); issue(3, 3);

    float acc[4][4][4] = {};
    const int KT = K / 16;
    int stg = 0, pstg = 4;
    for (int kt = 0; kt < KT; kt++) {
        if (kt <= KT - 4)      CP_WAIT(3);
        else if (kt == KT - 3) CP_WAIT(2);
        else if (kt == KT - 2) CP_WAIT(1);
        else                   CP_WAIT(0);
        __syncthreads();
        if (kt + 4 < KT) {
            issue(kt + 4, pstg);
            if (++pstg == NSTG) pstg = 0;
        }

        const __nv_bfloat16* AsT = As + stg * 128 * GST;
        const __nv_bfloat16* BsT = Bs + stg * 128 * GST;
        if (++stg == NSTG) stg = 0;

        uint32_t Bhf[8], Blf[8];
        ldsm4(Bhf[0], Bhf[1], Bhf[2], Bhf[3], smaddr(&BsT[bfr * GST + bfc]));
        ldsm4(Bhf[4], Bhf[5], Bhf[6], Bhf[7], smaddr(&BsT[(bfr + 16) * GST + bfc]));
        ldsm4(Blf[0], Blf[1], Blf[2], Blf[3], smaddr(&BsT[bfr * GST + bfc + 16]));
        ldsm4(Blf[4], Blf[5], Blf[6], Blf[7], smaddr(&BsT[(bfr + 16) * GST + bfc + 16]));

        #pragma unroll
        for (int h = 0; h < 2; h++) {
            uint32_t Ahf[2][4], Alf[2][4];
            #pragma unroll
            for (int m = 0; m < 2; m++) {
                const int mf = h * 2 + m;
                ldsm4(Ahf[m][0], Ahf[m][1], Ahf[m][2], Ahf[m][3],
                      smaddr(&AsT[(afr + mf * 16) * GST + afc]));
                ldsm4(Alf[m][0], Alf[m][1], Alf[m][2], Alf[m][3],
                      smaddr(&AsT[(afr + mf * 16) * GST + afc + 16]));
            }
            #pragma unroll
            for (int m = 0; m < 2; m++)
                #pragma unroll
                for (int nf = 0; nf < 4; nf++)
                    mma16816(acc[h * 2 + m][nf], Ahf[m], Bhf[nf * 2], Bhf[nf * 2 + 1]);
            #pragma unroll
            for (int m = 0; m < 2; m++)
                #pragma unroll
                for (int nf = 0; nf < 4; nf++)
                    mma16816(acc[h * 2 + m][nf], Ahf[m], Blf[nf * 2], Blf[nf * 2 + 1]);
            #pragma unroll
            for (int m = 0; m < 2; m++)
                #pragma unroll
                for (int nf = 0; nf < 4; nf++)
                    mma16816(acc[h * 2 + m][nf], Alf[m], Bhf[nf * 2], Bhf[nf * 2 + 1]);
        }
    }

    const int er = l >> 2, ec = (l & 3) * 2;
    #pragma unroll
    for (int mf = 0; mf < 4; mf++) {
        #pragma unroll
        for (int nf = 0; nf < 4; nf++) {
            const float* c = acc[mf][nf];
            const int rr = m0 + wm + mf * 16 + er;
            const int cc = n0 + wn + nf * 8 + ec;
            if (EPI == 1) {
                const int hh = cc >> 6, dd = cc & 63;
                const int bb = rr >> 11, ss = rr & (S - 1);
                const int rr2 = rr + 8, bb2 = rr2 >> 11, ss2 = rr2 & (S - 1);
                const size_t i0 = (((size_t)bb  * H + hh) * S + ss)  * DK + dd;
                const size_t i1 = (((size_t)bb2 * H + hh) * S + ss2) * DK + dd;
                __nv_bfloat16 h0 = __float2bfloat16(c[0]), h1 = __float2bfloat16(c[1]);
                __nv_bfloat16 h2 = __float2bfloat16(c[2]), h3 = __float2bfloat16(c[3]);
                *(uint32_t*)&ga.chi[zi][i0] = packbf(__bfloat162float(h0),
                                                     __bfloat162float(h1));
                *(uint32_t*)&ga.clo[zi][i0] = packbf(c[0] - __bfloat162float(h0),
                                                     c[1] - __bfloat162float(h1));
                *(uint32_t*)&ga.chi[zi][i1] = packbf(__bfloat162float(h2),
                                                     __bfloat162float(h3));
                *(uint32_t*)&ga.clo[zi][i1] = packbf(c[2] - __bfloat162float(h2),
                                                     c[3] - __bfloat162float(h3));
            } else {
                *(float2*)&ga.c[(size_t)rr * 1024 + cc] = make_float2(c[0], c[1]);
                *(float2*)&ga.c[(size_t)(rr + 8) * 1024 + cc] = make_float2(c[2], c[3]);
            }
        }
    }
}

// ---------------------------------------------------------------------------
// Attention pass 1 (rowsums): grid (S/64, 2 kslice, BH). 2-mma QK (K-hi only),
// 8 K-tiles per CTA, distance-2 prefetch, global atomic rowsum accumulation.
// ---------------------------------------------------------------------------
__global__ void __launch_bounds__(256, 2)
attn_pass1(const __nv_bfloat16* __restrict__ Qh, const __nv_bfloat16* __restrict__ Ql,
           const __nv_bfloat16* __restrict__ Kh, float* __restrict__ rs)
{
    extern __shared__ __align__(16) char smc[];
    __nv_bfloat16* Qs  = (__nv_bfloat16*)smc;
    __nv_bfloat16* KB0 = Qs + 64 * QST;
    __nv_bfloat16* KB1 = KB0 + 128 * KST;
    __nv_bfloat16* Vs  = KB1 + 128 * KST;

    const int z = blockIdx.z, y0 = blockIdx.x * 64, ks0 = blockIdx.y * 8;
    const size_t zb = (size_t)z * S * DK;

    const int tid = threadIdx.x, w = tid >> 5, l = tid & 31;
    const int wm = (w >> 1) * 16, wn = (w & 1) * 64;

    const int afr = (l & 15), afc = (l >> 4) * 8;
    const int bg = l >> 3, bRow = ((bg >> 1) << 3) + (l & 7), bc8 = (bg & 1) * 8;

    const int qrow = tid >> 2, qc = (tid & 3) * 16;
    const int krow = tid >> 1;

    // Q: hi to smem, lo staged in Vs then kept in registers
    {
        const __nv_bfloat16* s = Qh + zb + (size_t)(y0 + qrow) * DK + qc;
        const uint32_t d = smaddr(Qs + qrow * QST + qc);
        cpa16(d, s); cpa16(d + 16, s + 8);
        const __nv_bfloat16* s2 = Ql + zb + (size_t)(y0 + qrow) * DK + qc;
        const uint32_t d2 = smaddr(Vs + qrow * KST + qc);
        cpa16(d2, s2); cpa16(d2 + 16, s2 + 8);
        CP_COMMIT();
    }
    CP_WAIT(0); __syncthreads();
    uint32_t Alr[4][4];
    #pragma unroll
    for (int kk = 0; kk < 4; kk++)
        ldsm4(Alr[kk][0], Alr[kk][1], Alr[kk][2], Alr[kk][3],
              smaddr(&Vs[(wm + afr) * KST + kk * 16 + afc]));
    __syncthreads();

    auto issueKhi = [&](int kt, __nv_bfloat16* dst) {
        const int hf = tid & 1;
        const __nv_bfloat16* s = Kh + zb + (size_t)(kt * 128 + krow) * DK + hf * 32;
        const uint32_t d = smaddr(dst + krow * KST + hf * 32);
        #pragma unroll
        for (int i = 0; i < 4; i++) cpa16(d + i * 16, s + i * 8);
    };

    __nv_bfloat16* kb[3] = { KB0, KB1, Vs };
    issueKhi(ks0 + 0, kb[0]); CP_COMMIT();
    issueKhi(ks0 + 1, kb[1]); CP_COMMIT();

    float rp0 = 0.f, rp1 = 0.f;
    for (int t = 0; t < 8; t++) {
        if (t < 7) CP_WAIT(1); else CP_WAIT(0);
        __syncthreads();
        if (t + 2 < 8) { issueKhi(ks0 + t + 2, kb[(t + 2) % 3]); CP_COMMIT(); }
        const __nv_bfloat16* Kt = kb[t % 3];
        float Sacc[8][4] = {};
        #pragma unroll
        for (int kk = 0; kk < 4; kk++) {
            uint32_t Ah[4];
            ldsm4(Ah[0], Ah[1], Ah[2], Ah[3],
                  smaddr(&Qs[(wm + afr) * QST + kk * 16 + afc]));
            #pragma unroll
            for (int g = 0; g < 4; g++) {
                uint32_t Bh[4];
                ldsm4(Bh[0], Bh[1], Bh[2], Bh[3],
                      smaddr(&Kt[(wn + g * 16 + bRow) * KST + kk * 16 + bc8]));
                float* c0 = Sacc[2 * g];
                float* c1 = Sacc[2 * g + 1];
                mma16816(c0, Ah,      Bh[0], Bh[1]);
                mma16816(c1, Ah,      Bh[2], Bh[3]);
                mma16816(c0, Alr[kk], Bh[0], Bh[1]);
                mma16816(c1, Alr[kk], Bh[2], Bh[3]);
            }
        }
        #pragma unroll
        for (int nf = 0; nf < 8; nf++) {
            rp0 += __expf(Sacc[nf][0] * 0.125f) + __expf(Sacc[nf][1] * 0.125f);
            rp1 += __expf(Sacc[nf][2] * 0.125f) + __expf(Sacc[nf][3] * 0.125f);
        }
    }

    float v0 = rp0, v1 = rp1;
    v0 += __shfl_xor_sync(0xffffffffu, v0, 1);
    v0 += __shfl_xor_sync(0xffffffffu, v0, 2);
    v1 += __shfl_xor_sync(0xffffffffu, v1, 1);
    v1 += __shfl_xor_sync(0xffffffffu, v1, 2);
    if ((l & 3) == 0) {
        atomicAdd(&rs[(size_t)z * S + y0 + wm + (l >> 2)], v0);
        atomicAdd(&rs[(size_t)z * S + y0 + wm + (l >> 2) + 8], v1);
    }
}

// ---------------------------------------------------------------------------
// Attention pass 2: grid (S/64, 2 kslice, BH). 3-term QK + normalize/write
// attn + 3-term PV over the CTA's 8 K-tiles. Partial ctx (unscaled fp32) to
// per-slice buffer; exact partial P-sums atomically to rs2.
// ---------------------------------------------------------------------------
template <bool WRITE_E>
__global__ void __launch_bounds__(256, 2)
attn_pass2(const __nv_bfloat16* __restrict__ Qh, const __nv_bfloat16* __restrict__ Ql,
           const __nv_bfloat16* __restrict__ Kh, const __nv_bfloat16* __restrict__ Kl,
           const __nv_bfloat16* __restrict__ Vh, const __nv_bfloat16* __restrict__ Vl,
           const float* __restrict__ rs, float* __restrict__ rs2,
           float* __restrict__ ct0, float* __restrict__ ct1,
           float* __restrict__ attn)
{
    extern __shared__ __align__(16) char smc[];
    __nv_bfloat16* Qs  = (__nv_bfloat16*)smc;
    __nv_bfloat16* KB0 = Qs + 64 * QST;
    __nv_bfloat16* KB1 = KB0 + 128 * KST;
    __nv_bfloat16* Vs  = KB1 + 128 * KST;
    float* rbuf = (float*)KB0;

    const int z = blockIdx.z, y0 = blockIdx.x * 64, ks0 = blockIdx.y * 8;
    const int bz = z >> 4, hz = z & 15;
    const size_t zb = (size_t)z * S * DK;
    float* ctx = blockIdx.y ? ct1 : ct0;

    const int tid = threadIdx.x, w = tid >> 5, l = tid & 31;
    const int wm = (w >> 1) * 16, wn = (w & 1) * 64;

    const int afr = (l & 15), afc = (l >> 4) * 8;
    const int bg = l >> 3, bRow = ((bg >> 1) << 3) + (l & 7), bc8 = (bg & 1) * 8;
    const int vkr = ((l >> 3) & 1) * 8 + (l & 7), vnc = (l >> 4) * 8;

    const int qrow = tid >> 2, qc = (tid & 3) * 16;
    const int krow = tid >> 1;

    // Q: hi to smem, lo staged in Vs then kept in registers
    {
        const __nv_bfloat16* s = Qh + zb + (size_t)(y0 + qrow) * DK + qc;
        const uint32_t d = smaddr(Qs + qrow * QST + qc);
        cpa16(d, s); cpa16(d + 16, s + 8);
        const __nv_bfloat16* s2 = Ql + zb + (size_t)(y0 + qrow) * DK + qc;
        const uint32_t d2 = smaddr(Vs + qrow * KST + qc);
        cpa16(d2, s2); cpa16(d2 + 16, s2 + 8);
        CP_COMMIT();
    }
    CP_WAIT(0); __syncthreads();
    uint32_t Alr[4][4];
    #pragma unroll
    for (int kk = 0; kk < 4; kk++)
        ldsm4(Alr[kk][0], Alr[kk][1], Alr[kk][2], Alr[kk][3],
              smaddr(&Vs[(wm + afr) * KST + kk * 16 + afc]));
    __syncthreads();

    auto issueK = [&](int kt, __nv_bfloat16* dst) {
        const int pl = tid & 1;
        const __nv_bfloat16* s = (pl ? Kl : Kh) + zb + (size_t)(kt * 128 + krow) * DK;
        const uint32_t d = smaddr(dst + krow * KST + pl * 64);
        #pragma unroll
        for (int i = 0; i < 8; i++) cpa16(d + i * 16, s + i * 8);
    };
    auto issueV = [&](int kt) {
        const int pl = tid & 1;
        const __nv_bfloat16* s = (pl ? Vl : Vh) + zb + (size_t)(kt * 128 + krow) * DK;
        const uint32_t d = smaddr(Vs + krow * KST + pl * 64);
        #pragma unroll
        for (int i = 0; i < 8; i++) cpa16(d + i * 16, s + i * 8);
    };

    float inv0 = 1.0f, inv1 = 1.0f;
    if (WRITE_E) {
        inv0 = 1.0f / rs[(size_t)z * S + y0 + wm + (l >> 2)];
        inv1 = 1.0f / rs[(size_t)z * S + y0 + wm + (l >> 2) + 8];
    }

    float rp0 = 0.f, rp1 = 0.f;
    float acc[8][4] = {};
    issueK(ks0, KB0); CP_COMMIT();
    for (int t = 0; t < 8; t++) {
        CP_WAIT(0); __syncthreads();          // K(t) ready, PV(t-1) done
        const int kt = ks0 + t;
        issueV(kt); CP_COMMIT();
        const __nv_bfloat16* Kt = (t & 1) ? KB1 : KB0;

        float Sacc[8][4] = {};
        #pragma unroll
        for (int kk = 0; kk < 4; kk++) {
            uint32_t Ah[4];
            ldsm4(Ah[0], Ah[1], Ah[2], Ah[3],
                  smaddr(&Qs[(wm + afr) * QST + kk * 16 + afc]));
            #pragma unroll
            for (int g = 0; g < 4; g++) {
                uint32_t Bh[4], Bl[4];
                const int row = wn + g * 16 + bRow;
                ldsm4(Bh[0], Bh[1], Bh[2], Bh[3],
                      smaddr(&Kt[row * KST + kk * 16 + bc8]));
                ldsm4(Bl[0], Bl[1], Bl[2], Bl[3],
                      smaddr(&Kt[row * KST + 64 + kk * 16 + bc8]));
                float* c0 = Sacc[2 * g];
                float* c1 = Sacc[2 * g + 1];
                mma16816(c0, Ah,      Bh[0], Bh[1]);
                mma16816(c1, Ah,      Bh[2], Bh[3]);
                mma16816(c0, Ah,      Bl[0], Bl[1]);
                mma16816(c1, Ah,      Bl[2], Bl[3]);
                mma16816(c0, Alr[kk], Bh[0], Bh[1]);
                mma16816(c1, Alr[kk], Bh[2], Bh[3]);
            }
        }
        if (t < 7) { issueK(kt + 1, (t & 1) ? KB0 : KB1); CP_COMMIT(); }
        if (t < 7) CP_WAIT(1); else CP_WAIT(0);   // V(t) ready
        __syncthreads();

        #pragma unroll
        for (int j = 0; j < 4; j++) {
            uint32_t Aph[4], Apl[4];
            #pragma unroll
            for (int tt = 0; tt < 2; tt++) {
                float* c = Sacc[2 * j + tt];
                float e0 = __expf(c[0] * 0.125f), e1 = __expf(c[1] * 0.125f);
                float e2 = __expf(c[2] * 0.125f), e3 = __expf(c[3] * 0.125f);
                if (WRITE_E) { e0 *= inv0; e1 *= inv0; e2 *= inv1; e3 *= inv1; }
                rp0 += e0 + e1; rp1 += e2 + e3;
                __nv_bfloat16 h0 = __float2bfloat16(e0), h1 = __float2bfloat16(e1);
                __nv_bfloat16 h2 = __float2bfloat16(e2), h3 = __float2bfloat16(e3);
                Aph[2 * tt]     = packbf(__bfloat162float(h0), __bfloat162float(h1));
                Aph[2 * tt + 1] = packbf(__bfloat162float(h2), __bfloat162float(h3));
                Apl[2 * tt]     = packbf(e0 - __bfloat162float(h0), e1 - __bfloat162float(h1));
                Apl[2 * tt + 1] = packbf(e2 - __bfloat162float(h2), e3 - __bfloat162float(h3));
                if (WRITE_E) {
                    const int grow = y0 + wm + (l >> 2);
                    const int gcol = kt * 128 + wn + (2 * j + tt) * 8 + 2 * (l & 3);
                    *(float2*)&attn[((size_t)z * S + grow) * S + gcol] = make_float2(e0, e1);
                    *(float2*)&attn[((size_t)z * S + grow + 8) * S + gcol] = make_float2(e2, e3);
                }
            }
            #pragma unroll
            for (int g = 0; g < 4; g++) {
                uint32_t Vhf[4], Vlf[4];
                const int row = wn + j * 16 + vkr;
                ldsm4t(Vhf[0], Vhf[1], Vhf[2], Vhf[3],
                       smaddr(&Vs[row * KST + g * 16 + vnc]));
                ldsm4t(Vlf[0], Vlf[1], Vlf[2], Vlf[3],
                       smaddr(&Vs[row * KST + 64 + g * 16 + vnc]));
                float* c0 = acc[2 * g];
                float* c1 = acc[2 * g + 1];
                mma16816(c0, Aph, Vhf[0], Vhf[1]);
                mma16816(c1, Aph, Vhf[2], Vhf[3]);
                mma16816(c0, Aph, Vlf[0], Vlf[1]);
                mma16816(c1, Aph, Vlf[2], Vlf[3]);
                mma16816(c0, Apl, Vhf[0], Vhf[1]);
                mma16816(c1, Apl, Vhf[2], Vhf[3]);
            }
        }
    }

    // exact partial sums of written P -> rs2 (global)
    {
        float v0 = rp0, v1 = rp1;
        v0 += __shfl_xor_sync(0xffffffffu, v0, 1);
        v0 += __shfl_xor_sync(0xffffffffu, v0, 2);
        v1 += __shfl_xor_sync(0xffffffffu, v1, 1);
        v1 += __shfl_xor_sync(0xffffffffu, v1, 2);
        if ((l & 3) == 0) {
            atomicAdd(&rs2[(size_t)z * S + y0 + wm + (l >> 2)], v0);
            atomicAdd(&rs2[(size_t)z * S + y0 + wm + (l >> 2) + 8], v1);
        }
    }

    // pair-reduce ctx across the two k-half warps, write UNSCALED partials
    const int er = l >> 2;
    __syncthreads();
    if (w & 1) {
        #pragma unroll
        for (int nf = 0; nf < 8; nf++) {
            const int r = wm + er, c = nf * 8 + 2 * (l & 3);
            *(float2*)&rbuf[r * 66 + c] = make_float2(acc[nf][0], acc[nf][1]);
            *(float2*)&rbuf[(r + 8) * 66 + c] = make_float2(acc[nf][2], acc[nf][3]);
        }
    }
    __syncthreads();
    if (!(w & 1)) {
        const int r = wm + er;
        #pragma unroll
        for (int nf = 0; nf < 8; nf++) {
            const int c = nf * 8 + 2 * (l & 3);
            float2 p0 = *(float2*)&rbuf[r * 66 + c];
            float2 p1 = *(float2*)&rbuf[(r + 8) * 66 + c];
            *(float2*)&ctx[((size_t)bz * S + y0 + r) * D + hz * 64 + c] =
                make_float2(acc[nf][0] + p0.x, acc[nf][1] + p0.y);
            *(float2*)&ctx[((size_t)bz * S + y0 + r + 8) * D + hz * 64 + c] =
                make_float2(acc[nf][2] + p1.x, acc[nf][3] + p1.y);
        }
    }
}

// ---------------------------------------------------------------------------
extern "C" void kernel_launch(void* const* d_in, const int* in_sizes, int n_in,
                              void* d_out, int out_size)
{
    const float* query = (const float*)d_in[0];
    const float* key_i = (const float*)d_in[1];
    const float* value = (const float*)d_in[2];
    const float* w_q   = (const float*)d_in[3];
    const float* w_k   = (const float*)d_in[4];
    const float* w_v   = (const float*)d_in[5];
    const float* w_o   = (const float*)d_in[6];
    float* out = (float*)d_out;

    __nv_bfloat16 *xqh, *xql, *xkh, *xkl, *xvh, *xvl;
    __nv_bfloat16 *wqh, *wql, *wkh, *wkl, *wvh, *wvl, *woh, *wol;
    __nv_bfloat16 *cxh, *cxl;
    __nv_bfloat16 *qh, *ql, *kh, *kl, *vh, *vl;
    float *rs, *rs2, *ct0, *ct1;
    cudaGetSymbolAddress((void**)&xqh, g_xqh); cudaGetSymbolAddress((void**)&xql, g_xql);
    cudaGetSymbolAddress((void**)&xkh, g_xkh); cudaGetSymbolAddress((void**)&xkl, g_xkl);
    cudaGetSymbolAddress((void**)&xvh, g_xvh); cudaGetSymbolAddress((void**)&xvl, g_xvl);
    cudaGetSymbolAddress((void**)&wqh, g_wqh); cudaGetSymbolAddress((void**)&wql, g_wql);
    cudaGetSymbolAddress((void**)&wkh, g_wkh); cudaGetSymbolAddress((void**)&wkl, g_wkl);
    cudaGetSymbolAddress((void**)&wvh, g_wvh); cudaGetSymbolAddress((void**)&wvl, g_wvl);
    cudaGetSymbolAddress((void**)&woh, g_woh); cudaGetSymbolAddress((void**)&wol, g_wol);
    cudaGetSymbolAddress((void**)&cxh, g_cxh); cudaGetSymbolAddress((void**)&cxl, g_cxl);
    cudaGetSymbolAddress((void**)&qh, g_qh);   cudaGetSymbolAddress((void**)&ql, g_ql);
    cudaGetSymbolAddress((void**)&kh, g_kh);   cudaGetSymbolAddress((void**)&kl, g_kl);
    cudaGetSymbolAddress((void**)&vh, g_vh);   cudaGetSymbolAddress((void**)&vl, g_vl);
    cudaGetSymbolAddress((void**)&rs, g_rs);   cudaGetSymbolAddress((void**)&rs2, g_rs2);
    cudaGetSymbolAddress((void**)&ct0, g_ct0); cudaGetSymbolAddress((void**)&ct1, g_ct1);

    const bool want_attn = ((long long)out_size >= OUT_ELEMS + ATT_ELEMS);
    float* attn = want_attn ? (out + OUT_ELEMS) : nullptr;

    // ---- 0. zero rowsum accumulators ----
    zero_rs<<<(BH * S + 255) / 256, 256>>>(rs, rs2);

    // ---- 1. split fp32 inputs/weights into bf16 hi/lo planes ----
    ConvArgs ca{};
    ca.src[0] = query; ca.hi[0] = xqh; ca.lo[0] = xql; ca.n4[0] = (int)(OUT_ELEMS / 4);
    ca.src[1] = key_i; ca.hi[1] = xkh; ca.lo[1] = xkl; ca.n4[1] = (int)(OUT_ELEMS / 4);
    ca.src[2] = value; ca.hi[2] = xvh; ca.lo[2] = xvl; ca.n4[2] = (int)(OUT_ELEMS / 4);
    ca.src[3] = w_q;   ca.hi[3] = wqh; ca.lo[3] = wql; ca.n4[3] = D * D / 4;
    ca.src[4] = w_k;   ca.hi[4] = wkh; ca.lo[4] = wkl; ca.n4[4] = D * D / 4;
    ca.src[5] = w_v;   ca.hi[5] = wvh; ca.lo[5] = wvl; ca.n4[5] = D * D / 4;
    ca.src[6] = w_o;   ca.hi[6] = woh; ca.lo[6] = wol; ca.n4[6] = D * D / 4;
    convert_split<<<dim3((unsigned)(OUT_ELEMS / 4 / 256), 1, 7), 256>>>(ca);

    cudaFuncSetAttribute(gemm_bf16<1>, cudaFuncAttributeMaxDynamicSharedMemorySize, GSMEM);
    cudaFuncSetAttribute(gemm_bf16<0>, cudaFuncAttributeMaxDynamicSharedMemorySize, GSMEM);
    cudaFuncSetAttribute(attn_pass1, cudaFuncAttributeMaxDynamicSharedMemorySize, ASMEM);
    cudaFuncSetAttribute(attn_pass2<true>, cudaFuncAttributeMaxDynamicSharedMemorySize, ASMEM);
    cudaFuncSetAttribute(attn_pass2<false>, cudaFuncAttributeMaxDynamicSharedMemorySize, ASMEM);

    // ---- 2. q/k/v projections (one launch, grid.z=3) ----
    GemmArgs gp{};
    gp.ah[0] = xqh; gp.al[0] = xql; gp.bh[0] = wqh; gp.bl[0] = wql;
    gp.ah[1] = xkh; gp.al[1] = xkl; gp.bh[1] = wkh; gp.bl[1] = wkl;
    gp.ah[2] = xvh; gp.al[2] = xvl; gp.bh[2] = wvh; gp.bl[2] = wvl;
    gp.chi[0] = qh; gp.clo[0] = ql;
    gp.chi[1] = kh; gp.clo[1] = kl;
    gp.chi[2] = vh; gp.clo[2] = vl;
    gemm_bf16<1><<<dim3(8, 32, 3), 256, GSMEM>>>(gp);

    // ---- 3. attention: pass1 (rowsums) + pass2 (attn + partial ctx) ----
    const dim3 ga(S / 64, 2, BH);   // 2048 CTAs each
    if (want_attn) {
        attn_pass1<<<ga, 256, ASMEM>>>(qh, ql, kh, rs);
        attn_pass2<true><<<ga, 256, ASMEM>>>(qh, ql, kh, kl, vh, vl,
                                             rs, rs2, ct0, ct1, attn);
    } else {
        attn_pass2<false><<<ga, 256, ASMEM>>>(qh, ql, kh, kl, vh, vl,
                                              rs, rs2, ct0, ct1, nullptr);
    }

    // ---- 4. merge partial ctx -> normalized bf16 hi/lo planes ----
    merge_ctx<<<(unsigned)(OUT_ELEMS / 1024), 256>>>(ct0, ct1, rs2, cxh, cxl);

    // ---- 5. out = ctx @ Wo^T ----
    GemmArgs go{};
    go.ah[0] = cxh; go.al[0] = cxl; go.bh[0] = woh; go.bl[0] = wol;
    go.c = out;
    gemm_bf16<0><<<dim3(8, 32, 1), 256, GSMEM>>>(go);
}

// round 15
// speedup vs baseline: 1.0371x; 1.0371x over previous
#include <cuda_runtime.h>
#include <cuda_bf16.h>
#include <stdint.h>

// ---------------------------------------------------------------------------
// MultiHeadSelfAttention: B=2, S=2048, D=1024, H=16, dk=64
// R14: R12 arithmetic; DAG restructured. Projections launch = Q,K only.
//      One heterogeneous launch co-schedules V-projection tiles (first, LPT)
//      with attention pass-1 tiles (full-K, rowsums written directly).
//      Pass-2 = R12 fused minus pass1 (reads inv rowsums from global).
// ---------------------------------------------------------------------------

namespace {
constexpr int BATCH = 2, S = 2048, D = 1024, H = 16, DK = 64, BH = 32;
constexpr long long OUT_ELEMS = (long long)BATCH * S * D;          // 4,194,304
constexpr long long ATT_ELEMS = (long long)BH * S * (long long)S;  // 134,217,728
constexpr int QST = 72;     // attn: Q smem stride (hi plane) bf16
constexpr int KST = 136;    // attn: K/V smem stride bf16
constexpr int GST = 40;     // gemm smem stride bf16
constexpr int NSTG = 5;     // gemm cp.async stages
constexpr int GSMEM = NSTG * 128 * GST * 2 * 2;            // 102400 B
constexpr int ASMEM = (64 * QST + 3 * 128 * KST) * 2 + 128 * 4;  // 114176 B
}

// ---- scratch (allocation-free __device__ globals) ----
__device__ __nv_bfloat16 g_xqh[(size_t)BATCH * S * D], g_xql[(size_t)BATCH * S * D];
__device__ __nv_bfloat16 g_xkh[(size_t)BATCH * S * D], g_xkl[(size_t)BATCH * S * D];
__device__ __nv_bfloat16 g_xvh[(size_t)BATCH * S * D], g_xvl[(size_t)BATCH * S * D];
__device__ __nv_bfloat16 g_wqh[(size_t)D * D], g_wql[(size_t)D * D];
__device__ __nv_bfloat16 g_wkh[(size_t)D * D], g_wkl[(size_t)D * D];
__device__ __nv_bfloat16 g_wvh[(size_t)D * D], g_wvl[(size_t)D * D];
__device__ __nv_bfloat16 g_woh[(size_t)D * D], g_wol[(size_t)D * D];
__device__ __nv_bfloat16 g_cxh[(size_t)BATCH * S * D], g_cxl[(size_t)BATCH * S * D];
__device__ __nv_bfloat16 g_qh[(size_t)BH * S * DK], g_ql[(size_t)BH * S * DK];
__device__ __nv_bfloat16 g_kh[(size_t)BH * S * DK], g_kl[(size_t)BH * S * DK];
__device__ __nv_bfloat16 g_vh[(size_t)BH * S * DK], g_vl[(size_t)BH * S * DK];
__device__ float g_rs[(size_t)BH * S];     // pass1 inverse rowsums

// ------------------------------ PTX helpers --------------------------------
__device__ __forceinline__ uint32_t smaddr(const void* p) {
    return (uint32_t)__cvta_generic_to_shared(p);
}
__device__ __forceinline__ void ldsm4(uint32_t& r0, uint32_t& r1, uint32_t& r2,
                                      uint32_t& r3, uint32_t a) {
    asm volatile("ldmatrix.sync.aligned.m8n8.x4.shared.b16 {%0,%1,%2,%3}, [%4];"
                 : "=r"(r0), "=r"(r1), "=r"(r2), "=r"(r3) : "r"(a));
}
__device__ __forceinline__ void ldsm4t(uint32_t& r0, uint32_t& r1, uint32_t& r2,
                                       uint32_t& r3, uint32_t a) {
    asm volatile("ldmatrix.sync.aligned.m8n8.x4.trans.shared.b16 {%0,%1,%2,%3}, [%4];"
                 : "=r"(r0), "=r"(r1), "=r"(r2), "=r"(r3) : "r"(a));
}
__device__ __forceinline__ void mma16816(float* c, const uint32_t* a,
                                         uint32_t b0, uint32_t b1) {
    asm volatile("mma.sync.aligned.m16n8k16.row.col.f32.bf16.bf16.f32 "
                 "{%0,%1,%2,%3}, {%4,%5,%6,%7}, {%8,%9}, {%0,%1,%2,%3};"
                 : "+f"(c[0]), "+f"(c[1]), "+f"(c[2]), "+f"(c[3])
                 : "r"(a[0]), "r"(a[1]), "r"(a[2]), "r"(a[3]), "r"(b0), "r"(b1));
}
__device__ __forceinline__ uint32_t packbf(float a, float b) {
    __nv_bfloat162 t = __halves2bfloat162(__float2bfloat16(a), __float2bfloat16(b));
    return *reinterpret_cast<uint32_t*>(&t);
}
__device__ __forceinline__ void cpa16(uint32_t dst, const void* src) {
    asm volatile("cp.async.cg.shared.global [%0], [%1], 16;" :: "r"(dst), "l"(src));
}
#define CP_COMMIT() asm volatile("cp.async.commit_group;")
#define CP_WAIT(N)  asm volatile("cp.async.wait_group %0;" :: "n"(N))

__device__ __forceinline__ void split4(const float4 f, uint2& hi, uint2& lo) {
    __nv_bfloat16 hx = __float2bfloat16(f.x), hy = __float2bfloat16(f.y);
    __nv_bfloat16 hz = __float2bfloat16(f.z), hw = __float2bfloat16(f.w);
    __nv_bfloat16 lx = __float2bfloat16(f.x - __bfloat162float(hx));
    __nv_bfloat16 ly = __float2bfloat16(f.y - __bfloat162float(hy));
    __nv_bfloat16 lz = __float2bfloat16(f.z - __bfloat162float(hz));
    __nv_bfloat16 lw = __float2bfloat16(f.w - __bfloat162float(hw));
    __nv_bfloat162 h01 = __halves2bfloat162(hx, hy), h23 = __halves2bfloat162(hz, hw);
    __nv_bfloat162 l01 = __halves2bfloat162(lx, ly), l23 = __halves2bfloat162(lz, lw);
    hi.x = *reinterpret_cast<uint32_t*>(&h01); hi.y = *reinterpret_cast<uint32_t*>(&h23);
    lo.x = *reinterpret_cast<uint32_t*>(&l01); lo.y = *reinterpret_cast<uint32_t*>(&l23);
}

// ---------------------------------------------------------------------------
// Elementwise fp32 -> bf16 hi/lo plane split. grid.z selects tensor.
// ---------------------------------------------------------------------------
struct ConvArgs {
    const float* src[8];
    __nv_bfloat16* hi[8];
    __nv_bfloat16* lo[8];
    int n4[8];
};

__global__ void __launch_bounds__(256)
convert_split(ConvArgs a)
{
    const int z = blockIdx.z;
    const int idx = blockIdx.x * 256 + threadIdx.x;
    if (idx >= a.n4[z]) return;
    float4 f = ((const float4*)a.src[z])[idx];
    uint2 hi, lo;
    split4(f, hi, lo);
    ((uint2*)a.hi[z])[idx] = hi;
    ((uint2*)a.lo[z])[idx] = lo;
}

// ---------------------------------------------------------------------------
// Dense NT GEMM tile body (device fn). 128x128 tile, BK=16, NSTG=5 cp.async,
// 8 warps (64x32 warp tiles), term-major 3-term hi/lo mma (R12, 109 us/unit).
// EPI=1: bf16 hi/lo planes head-major [B,H,S,DK]; EPI=0: fp32 C row-major.
// ---------------------------------------------------------------------------
template <int EPI>
__device__ __forceinline__ void gemm_tile(
    const __nv_bfloat16* __restrict__ Ah, const __nv_bfloat16* __restrict__ Al,
    const __nv_bfloat16* __restrict__ Bh, const __nv_bfloat16* __restrict__ Bl,
    float* __restrict__ C, __nv_bfloat16* __restrict__ Chi,
    __nv_bfloat16* __restrict__ Clo, int m0, int n0, __nv_bfloat16* sm)
{
    constexpr int K = 1024;
    __nv_bfloat16* As = sm;
    __nv_bfloat16* Bs = sm + NSTG * 128 * GST;

    const int tid = threadIdx.x, w = tid >> 5, l = tid & 31;
    const int wm = (w >> 2) * 64, wn = (w & 3) * 32;

    const int lrow = tid & 127, lpl = tid >> 7;
    const __nv_bfloat16* srcA = (lpl ? Al : Ah) + (size_t)(m0 + lrow) * K;
    const __nv_bfloat16* srcB = (lpl ? Bl : Bh) + (size_t)(n0 + lrow) * K;

    auto issue = [&](int kt, int stg) {
        const uint32_t da = smaddr(As + (stg * 128 + lrow) * GST + lpl * 16);
        const __nv_bfloat16* sa = srcA + kt * 16;
        cpa16(da, sa); cpa16(da + 16, sa + 8);
        const uint32_t db = smaddr(Bs + (stg * 128 + lrow) * GST + lpl * 16);
        const __nv_bfloat16* sb = srcB + kt * 16;
        cpa16(db, sb); cpa16(db + 16, sb + 8);
        CP_COMMIT();
    };

    const int afr = wm + (l & 15);
    const int afc = (l >> 4) * 8;
    const int bg  = l >> 3;
    const int bfr = wn + ((bg >> 1) << 3) + (l & 7);
    const int bfc = (bg & 1) * 8;

    issue(0, 0); issue(1, 1); issue(2, 2); issue(3, 3);

    float acc[4][4][4] = {};
    const int KT = K / 16;
    int stg = 0, pstg = 4;
    for (int kt = 0; kt < KT; kt++) {
        if (kt <= KT - 4)      CP_WAIT(3);
        else if (kt == KT - 3) CP_WAIT(2);
        else if (kt == KT - 2) CP_WAIT(1);
        else                   CP_WAIT(0);
        __syncthreads();
        if (kt + 4 < KT) {
            issue(kt + 4, pstg);
            if (++pstg == NSTG) pstg = 0;
        }

        const __nv_bfloat16* AsT = As + stg * 128 * GST;
        const __nv_bfloat16* BsT = Bs + stg * 128 * GST;
        if (++stg == NSTG) stg = 0;

        uint32_t Bhf[8], Blf[8];
        ldsm4(Bhf[0], Bhf[1], Bhf[2], Bhf[3], smaddr(&BsT[bfr * GST + bfc]));
        ldsm4(Bhf[4], Bhf[5], Bhf[6], Bhf[7], smaddr(&BsT[(bfr + 16) * GST + bfc]));
        ldsm4(Blf[0], Blf[1], Blf[2], Blf[3], smaddr(&BsT[bfr * GST + bfc + 16]));
        ldsm4(Blf[4], Blf[5], Blf[6], Blf[7], smaddr(&BsT[(bfr + 16) * GST + bfc + 16]));

        #pragma unroll
        for (int h = 0; h < 2; h++) {
            uint32_t Ahf[2][4], Alf[2][4];
            #pragma unroll
            for (int m = 0; m < 2; m++) {
                const int mf = h * 2 + m;
                ldsm4(Ahf[m][0], Ahf[m][1], Ahf[m][2], Ahf[m][3],
                      smaddr(&AsT[(afr + mf * 16) * GST + afc]));
                ldsm4(Alf[m][0], Alf[m][1], Alf[m][2], Alf[m][3],
                      smaddr(&AsT[(afr + mf * 16) * GST + afc + 16]));
            }
            #pragma unroll
            for (int m = 0; m < 2; m++)
                #pragma unroll
                for (int nf = 0; nf < 4; nf++)
                    mma16816(acc[h * 2 + m][nf], Ahf[m], Bhf[nf * 2], Bhf[nf * 2 + 1]);
            #pragma unroll
            for (int m = 0; m < 2; m++)
                #pragma unroll
                for (int nf = 0; nf < 4; nf++)
                    mma16816(acc[h * 2 + m][nf], Ahf[m], Blf[nf * 2], Blf[nf * 2 + 1]);
            #pragma unroll
            for (int m = 0; m < 2; m++)
                #pragma unroll
                for (int nf = 0; nf < 4; nf++)
                    mma16816(acc[h * 2 + m][nf], Alf[m], Bhf[nf * 2], Bhf[nf * 2 + 1]);
        }
    }

    const int er = l >> 2, ec = (l & 3) * 2;
    #pragma unroll
    for (int mf = 0; mf < 4; mf++) {
        #pragma unroll
        for (int nf = 0; nf < 4; nf++) {
            const float* c = acc[mf][nf];
            const int rr = m0 + wm + mf * 16 + er;
            const int cc = n0 + wn + nf * 8 + ec;
            if (EPI == 1) {
                const int hh = cc >> 6, dd = cc & 63;
                const int bb = rr >> 11, ss = rr & (S - 1);
                const int rr2 = rr + 8, bb2 = rr2 >> 11, ss2 = rr2 & (S - 1);
                const size_t i0 = (((size_t)bb  * H + hh) * S + ss)  * DK + dd;
                const size_t i1 = (((size_t)bb2 * H + hh) * S + ss2) * DK + dd;
                __nv_bfloat16 h0 = __float2bfloat16(c[0]), h1 = __float2bfloat16(c[1]);
                __nv_bfloat16 h2 = __float2bfloat16(c[2]), h3 = __float2bfloat16(c[3]);
                *(uint32_t*)&Chi[i0] = packbf(__bfloat162float(h0), __bfloat162float(h1));
                *(uint32_t*)&Clo[i0] = packbf(c[0] - __bfloat162float(h0),
                                              c[1] - __bfloat162float(h1));
                *(uint32_t*)&Chi[i1] = packbf(__bfloat162float(h2), __bfloat162float(h3));
                *(uint32_t*)&Clo[i1] = packbf(c[2] - __bfloat162float(h2),
                                              c[3] - __bfloat162float(h3));
            } else {
                *(float2*)&C[(size_t)rr * 1024 + cc] = make_float2(c[0], c[1]);
                *(float2*)&C[(size_t)(rr + 8) * 1024 + cc] = make_float2(c[2], c[3]);
            }
        }
    }
}

struct GemmArgs {
    const __nv_bfloat16 *ah[3], *al[3], *bh[3], *bl[3];
    float* c;
    __nv_bfloat16 *chi[3], *clo[3];
};

template <int EPI>
__global__ void __launch_bounds__(256, 2)
gemm_bf16(GemmArgs ga)
{
    extern __shared__ __align__(16) __nv_bfloat16 sm[];
    const int zi = blockIdx.z;
    gemm_tile<EPI>(ga.ah[zi], ga.al[zi], ga.bh[zi], ga.bl[zi],
                   ga.c, ga.chi[zi], ga.clo[zi],
                   blockIdx.y * 128, blockIdx.x * 128, sm);
}

// ---------------------------------------------------------------------------
// Heterogeneous launch: blocks [0,256) = V projection tiles (LPT: long jobs
// first); blocks [256, 256+1024) = attention pass-1 tiles (full K range,
// inverse rowsums written directly to rs — no atomics/zeroing).
// ---------------------------------------------------------------------------
__global__ void __launch_bounds__(256, 2)
pass1_vproj(const __nv_bfloat16* __restrict__ Qh, const __nv_bfloat16* __restrict__ Ql,
            const __nv_bfloat16* __restrict__ Kh, float* __restrict__ rs,
            const __nv_bfloat16* __restrict__ xvh, const __nv_bfloat16* __restrict__ xvl,
            const __nv_bfloat16* __restrict__ wvh, const __nv_bfloat16* __restrict__ wvl,
            __nv_bfloat16* __restrict__ vh, __nv_bfloat16* __restrict__ vl)
{
    extern __shared__ __align__(16) char smc[];

    if (blockIdx.x < 256) {
        // ---- V projection tile ----
        const int t = blockIdx.x;
        gemm_tile<1>(xvh, xvl, wvh, wvl, nullptr, vh, vl,
                     (t >> 3) * 128, (t & 7) * 128, (__nv_bfloat16*)smc);
        return;
    }

    // ---- attention pass 1 tile ----
    __nv_bfloat16* Qs  = (__nv_bfloat16*)smc;
    __nv_bfloat16* KB0 = Qs + 64 * QST;
    __nv_bfloat16* KB1 = KB0 + 128 * KST;
    __nv_bfloat16* Vs  = KB1 + 128 * KST;
    float* rsm = (float*)(Vs + 128 * KST);

    const int bt = blockIdx.x - 256;
    const int z = bt >> 5, y0 = (bt & 31) * 64;
    const size_t zb = (size_t)z * S * DK;

    const int tid = threadIdx.x, w = tid >> 5, l = tid & 31;
    const int wm = (w >> 1) * 16, wn = (w & 1) * 64;

    const int afr = (l & 15), afc = (l >> 4) * 8;
    const int bg = l >> 3, bRow = ((bg >> 1) << 3) + (l & 7), bc8 = (bg & 1) * 8;

    const int qrow = tid >> 2, qc = (tid & 3) * 16;
    const int krow = tid >> 1;

    if (tid < 64) rsm[tid] = 0.0f;

    // Q: hi to smem, lo staged in Vs then kept in registers
    {
        const __nv_bfloat16* s = Qh + zb + (size_t)(y0 + qrow) * DK + qc;
        const uint32_t d = smaddr(Qs + qrow * QST + qc);
        cpa16(d, s); cpa16(d + 16, s + 8);
        const __nv_bfloat16* s2 = Ql + zb + (size_t)(y0 + qrow) * DK + qc;
        const uint32_t d2 = smaddr(Vs + qrow * KST + qc);
        cpa16(d2, s2); cpa16(d2 + 16, s2 + 8);
        CP_COMMIT();
    }
    CP_WAIT(0); __syncthreads();
    uint32_t Alr[4][4];
    #pragma unroll
    for (int kk = 0; kk < 4; kk++)
        ldsm4(Alr[kk][0], Alr[kk][1], Alr[kk][2], Alr[kk][3],
              smaddr(&Vs[(wm + afr) * KST + kk * 16 + afc]));
    __syncthreads();

    auto issueKhi = [&](int kt, __nv_bfloat16* dst) {
        const int hf = tid & 1;
        const __nv_bfloat16* s = Kh + zb + (size_t)(kt * 128 + krow) * DK + hf * 32;
        const uint32_t d = smaddr(dst + krow * KST + hf * 32);
        #pragma unroll
        for (int i = 0; i < 4; i++) cpa16(d + i * 16, s + i * 8);
    };

    __nv_bfloat16* kb[3] = { KB0, KB1, Vs };
    issueKhi(0, kb[0]); CP_COMMIT();
    issueKhi(1, kb[1]); CP_COMMIT();

    float rp0 = 0.f, rp1 = 0.f;
    for (int kt = 0; kt < 16; kt++) {
        if (kt < 15) CP_WAIT(1); else CP_WAIT(0);
        __syncthreads();
        if (kt + 2 < 16) { issueKhi(kt + 2, kb[(kt + 2) % 3]); CP_COMMIT(); }
        const __nv_bfloat16* Kt = kb[kt % 3];
        float Sacc[8][4] = {};
        #pragma unroll
        for (int kk = 0; kk < 4; kk++) {
            uint32_t Ah[4];
            ldsm4(Ah[0], Ah[1], Ah[2], Ah[3],
                  smaddr(&Qs[(wm + afr) * QST + kk * 16 + afc]));
            #pragma unroll
            for (int g = 0; g < 4; g++) {
                uint32_t Bh[4];
                ldsm4(Bh[0], Bh[1], Bh[2], Bh[3],
                      smaddr(&Kt[(wn + g * 16 + bRow) * KST + kk * 16 + bc8]));
                float* c0 = Sacc[2 * g];
                float* c1 = Sacc[2 * g + 1];
                mma16816(c0, Ah,      Bh[0], Bh[1]);
                mma16816(c1, Ah,      Bh[2], Bh[3]);
                mma16816(c0, Alr[kk], Bh[0], Bh[1]);
                mma16816(c1, Alr[kk], Bh[2], Bh[3]);
            }
        }
        #pragma unroll
        for (int nf = 0; nf < 8; nf++) {
            rp0 += __expf(Sacc[nf][0] * 0.125f) + __expf(Sacc[nf][1] * 0.125f);
            rp1 += __expf(Sacc[nf][2] * 0.125f) + __expf(Sacc[nf][3] * 0.125f);
        }
    }

    float v0 = rp0, v1 = rp1;
    v0 += __shfl_xor_sync(0xffffffffu, v0, 1);
    v0 += __shfl_xor_sync(0xffffffffu, v0, 2);
    v1 += __shfl_xor_sync(0xffffffffu, v1, 1);
    v1 += __shfl_xor_sync(0xffffffffu, v1, 2);
    if ((l & 3) == 0) {
        atomicAdd(&rsm[wm + (l >> 2)], v0);
        atomicAdd(&rsm[wm + (l >> 2) + 8], v1);
    }
    __syncthreads();
    if (tid < 64) rs[(size_t)z * S + y0 + tid] = 1.0f / rsm[tid];
}

// ---------------------------------------------------------------------------
// Attention pass 2 (R12 fused minus pass1). Grid (S/64, BH); 2 CTAs/SM.
// 3-term QK + normalized attn write + 3-term PV; exact local ctx norm (rsm2);
// ctx emitted as bf16 hi/lo planes.
// ---------------------------------------------------------------------------
template <bool WRITE_E>
__global__ void __launch_bounds__(256, 2)
attn_pass2(const __nv_bfloat16* __restrict__ Qh, const __nv_bfloat16* __restrict__ Ql,
           const __nv_bfloat16* __restrict__ Kh, const __nv_bfloat16* __restrict__ Kl,
           const __nv_bfloat16* __restrict__ Vh, const __nv_bfloat16* __restrict__ Vl,
           const float* __restrict__ rs,
           __nv_bfloat16* __restrict__ cxh, __nv_bfloat16* __restrict__ cxl,
           float* __restrict__ attn)
{
    extern __shared__ __align__(16) char smc[];
    __nv_bfloat16* Qs  = (__nv_bfloat16*)smc;
    __nv_bfloat16* KB0 = Qs + 64 * QST;
    __nv_bfloat16* KB1 = KB0 + 128 * KST;
    __nv_bfloat16* Vs  = KB1 + 128 * KST;
    float* rsm  = (float*)(Vs + 128 * KST);
    float* rsm2 = rsm + 64;
    float* rbuf = (float*)KB0;

    const int z = blockIdx.y, y0 = blockIdx.x * 64;
    const int bz = z >> 4, hz = z & 15;
    const size_t zb = (size_t)z * S * DK;

    const int tid = threadIdx.x, w = tid >> 5, l = tid & 31;
    const int wm = (w >> 1) * 16, wn = (w & 1) * 64;

    const int afr = (l & 15), afc = (l >> 4) * 8;
    const int bg = l >> 3, bRow = ((bg >> 1) << 3) + (l & 7), bc8 = (bg & 1) * 8;
    const int vkr = ((l >> 3) & 1) * 8 + (l & 7), vnc = (l >> 4) * 8;

    const int qrow = tid >> 2, qc = (tid & 3) * 16;
    const int krow = tid >> 1;

    if (tid < 64) rsm2[tid] = 0.0f;

    {
        const __nv_bfloat16* s = Qh + zb + (size_t)(y0 + qrow) * DK + qc;
        const uint32_t d = smaddr(Qs + qrow * QST + qc);
        cpa16(d, s); cpa16(d + 16, s + 8);
        const __nv_bfloat16* s2 = Ql + zb + (size_t)(y0 + qrow) * DK + qc;
        const uint32_t d2 = smaddr(Vs + qrow * KST + qc);
        cpa16(d2, s2); cpa16(d2 + 16, s2 + 8);
        CP_COMMIT();
    }
    CP_WAIT(0); __syncthreads();
    uint32_t Alr[4][4];
    #pragma unroll
    for (int kk = 0; kk < 4; kk++)
        ldsm4(Alr[kk][0], Alr[kk][1], Alr[kk][2], Alr[kk][3],
              smaddr(&Vs[(wm + afr) * KST + kk * 16 + afc]));
    __syncthreads();

    auto issueK = [&](int kt, __nv_bfloat16* dst) {
        const int pl = tid & 1;
        const __nv_bfloat16* s = (pl ? Kl : Kh) + zb + (size_t)(kt * 128 + krow) * DK;
        const uint32_t d = smaddr(dst + krow * KST + pl * 64);
        #pragma unroll
        for (int i = 0; i < 8; i++) cpa16(d + i * 16, s + i * 8);
    };
    auto issueV = [&](int kt) {
        const int pl = tid & 1;
        const __nv_bfloat16* s = (pl ? Vl : Vh) + zb + (size_t)(kt * 128 + krow) * DK;
        const uint32_t d = smaddr(Vs + krow * KST + pl * 64);
        #pragma unroll
        for (int i = 0; i < 8; i++) cpa16(d + i * 16, s + i * 8);
    };

    float inv0 = 1.0f, inv1 = 1.0f;
    if (WRITE_E) {
        inv0 = rs[(size_t)z * S + y0 + wm + (l >> 2)];
        inv1 = rs[(size_t)z * S + y0 + wm + (l >> 2) + 8];
    }

    float rp0 = 0.f, rp1 = 0.f;
    float acc[8][4] = {};
    issueK(0, KB0); CP_COMMIT();
    for (int kt = 0; kt < 16; kt++) {
        CP_WAIT(0); __syncthreads();
        issueV(kt); CP_COMMIT();
        const __nv_bfloat16* Kt = (kt & 1) ? KB1 : KB0;

        float Sacc[8][4] = {};
        #pragma unroll
        for (int kk = 0; kk < 4; kk++) {
            uint32_t Ah[4];
            ldsm4(Ah[0], Ah[1], Ah[2], Ah[3],
                  smaddr(&Qs[(wm + afr) * QST + kk * 16 + afc]));
            #pragma unroll
            for (int g = 0; g < 4; g++) {
                uint32_t Bh[4], Bl[4];
                const int row = wn + g * 16 + bRow;
                ldsm4(Bh[0], Bh[1], Bh[2], Bh[3],
                      smaddr(&Kt[row * KST + kk * 16 + bc8]));
                ldsm4(Bl[0], Bl[1], Bl[2], Bl[3],
                      smaddr(&Kt[row * KST + 64 + kk * 16 + bc8]));
                float* c0 = Sacc[2 * g];
                float* c1 = Sacc[2 * g + 1];
                mma16816(c0, Ah,      Bh[0], Bh[1]);
                mma16816(c1, Ah,      Bh[2], Bh[3]);
                mma16816(c0, Ah,      Bl[0], Bl[1]);
                mma16816(c1, Ah,      Bl[2], Bl[3]);
                mma16816(c0, Alr[kk], Bh[0], Bh[1]);
                mma16816(c1, Alr[kk], Bh[2], Bh[3]);
            }
        }
        if (kt < 15) { issueK(kt + 1, (kt & 1) ? KB0 : KB1); CP_COMMIT(); }
        if (kt < 15) CP_WAIT(1); else CP_WAIT(0);
        __syncthreads();

        #pragma unroll
        for (int j = 0; j < 4; j++) {
            uint32_t Aph[4], Apl[4];
            #pragma unroll
            for (int t = 0; t < 2; t++) {
                float* c = Sacc[2 * j + t];
                float e0 = __expf(c[0] * 0.125f), e1 = __expf(c[1] * 0.125f);
                float e2 = __expf(c[2] * 0.125f), e3 = __expf(c[3] * 0.125f);
                if (WRITE_E) { e0 *= inv0; e1 *= inv0; e2 *= inv1; e3 *= inv1; }
                rp0 += e0 + e1; rp1 += e2 + e3;
                __nv_bfloat16 h0 = __float2bfloat16(e0), h1 = __float2bfloat16(e1);
                __nv_bfloat16 h2 = __float2bfloat16(e2), h3 = __float2bfloat16(e3);
                Aph[2 * t]     = packbf(__bfloat162float(h0), __bfloat162float(h1));
                Aph[2 * t + 1] = packbf(__bfloat162float(h2), __bfloat162float(h3));
                Apl[2 * t]     = packbf(e0 - __bfloat162float(h0), e1 - __bfloat162float(h1));
                Apl[2 * t + 1] = packbf(e2 - __bfloat162float(h2), e3 - __bfloat162float(h3));
                if (WRITE_E) {
                    const int grow = y0 + wm + (l >> 2);
                    const int gcol = kt * 128 + wn + (2 * j + t) * 8 + 2 * (l & 3);
                    *(float2*)&attn[((size_t)z * S + grow) * S + gcol] = make_float2(e0, e1);
                    *(float2*)&attn[((size_t)z * S + grow + 8) * S + gcol] = make_float2(e2, e3);
                }
            }
            #pragma unroll
            for (int g = 0; g < 4; g++) {
                uint32_t Vhf[4], Vlf[4];
                const int row = wn + j * 16 + vkr;
                ldsm4t(Vhf[0], Vhf[1], Vhf[2], Vhf[3],
                       smaddr(&Vs[row * KST + g * 16 + vnc]));
                ldsm4t(Vlf[0], Vlf[1], Vlf[2], Vlf[3],
                       smaddr(&Vs[row * KST + 64 + g * 16 + vnc]));
                float* c0 = acc[2 * g];
                float* c1 = acc[2 * g + 1];
                mma16816(c0, Aph, Vhf[0], Vhf[1]);
                mma16816(c1, Aph, Vhf[2], Vhf[3]);
                mma16816(c0, Aph, Vlf[0], Vlf[1]);
                mma16816(c1, Aph, Vlf[2], Vlf[3]);
                mma16816(c0, Apl, Vhf[0], Vhf[1]);
                mma16816(c1, Apl, Vhf[2], Vhf[3]);
            }
        }
    }

    // ---- exact row sums of (pre-normalized) P -> rsm2 ----
    {
        float v0 = rp0, v1 = rp1;
        v0 += __shfl_xor_sync(0xffffffffu, v0, 1);
        v0 += __shfl_xor_sync(0xffffffffu, v0, 2);
        v1 += __shfl_xor_sync(0xffffffffu, v1, 1);
        v1 += __shfl_xor_sync(0xffffffffu, v1, 2);
        if ((l & 3) == 0) {
            atomicAdd(&rsm2[wm + (l >> 2)], v0);
            atomicAdd(&rsm2[wm + (l >> 2) + 8], v1);
        }
    }
    __syncthreads();
    if (tid < 64) rsm2[tid] = 1.0f / rsm2[tid];
    __syncthreads();

    // ---- pair-reduce ctx, exact scale, write as bf16 hi/lo planes ----
    const int er = l >> 2;
    if (w & 1) {
        #pragma unroll
        for (int nf = 0; nf < 8; nf++) {
            const int r = wm + er, c = nf * 8 + 2 * (l & 3);
            *(float2*)&rbuf[r * 66 + c] = make_float2(acc[nf][0], acc[nf][1]);
            *(float2*)&rbuf[(r + 8) * 66 + c] = make_float2(acc[nf][2], acc[nf][3]);
        }
    }
    __syncthreads();
    if (!(w & 1)) {
        const int r = wm + er;
        const float s0 = rsm2[r], s1 = rsm2[r + 8];
        #pragma unroll
        for (int nf = 0; nf < 8; nf++) {
            const int c = nf * 8 + 2 * (l & 3);
            float2 p0 = *(float2*)&rbuf[r * 66 + c];
            float2 p1 = *(float2*)&rbuf[(r + 8) * 66 + c];
            float o0 = (acc[nf][0] + p0.x) * s0, o1 = (acc[nf][1] + p0.y) * s0;
            float o2 = (acc[nf][2] + p1.x) * s1, o3 = (acc[nf][3] + p1.y) * s1;
            const size_t i0 = ((size_t)bz * S + y0 + r) * D + hz * 64 + c;
            const size_t i1 = ((size_t)bz * S + y0 + r + 8) * D + hz * 64 + c;
            __nv_bfloat16 h0 = __float2bfloat16(o0), h1 = __float2bfloat16(o1);
            __nv_bfloat16 h2 = __float2bfloat16(o2), h3 = __float2bfloat16(o3);
            *(uint32_t*)&cxh[i0] = packbf(__bfloat162float(h0), __bfloat162float(h1));
            *(uint32_t*)&cxl[i0] = packbf(o0 - __bfloat162float(h0),
                                          o1 - __bfloat162float(h1));
            *(uint32_t*)&cxh[i1] = packbf(__bfloat162float(h2), __bfloat162float(h3));
            *(uint32_t*)&cxl[i1] = packbf(o2 - __bfloat162float(h2),
                                          o3 - __bfloat162float(h3));
        }
    }
}

// ---------------------------------------------------------------------------
extern "C" void kernel_launch(void* const* d_in, const int* in_sizes, int n_in,
                              void* d_out, int out_size)
{
    const float* query = (const float*)d_in[0];
    const float* key_i = (const float*)d_in[1];
    const float* value = (const float*)d_in[2];
    const float* w_q   = (const float*)d_in[3];
    const float* w_k   = (const float*)d_in[4];
    const float* w_v   = (const float*)d_in[5];
    const float* w_o   = (const float*)d_in[6];
    float* out = (float*)d_out;

    __nv_bfloat16 *xqh, *xql, *xkh, *xkl, *xvh, *xvl;
    __nv_bfloat16 *wqh, *wql, *wkh, *wkl, *wvh, *wvl, *woh, *wol;
    __nv_bfloat16 *cxh, *cxl;
    __nv_bfloat16 *qh, *ql, *kh, *kl, *vh, *vl;
    float *rs;
    cudaGetSymbolAddress((void**)&xqh, g_xqh); cudaGetSymbolAddress((void**)&xql, g_xql);
    cudaGetSymbolAddress((void**)&xkh, g_xkh); cudaGetSymbolAddress((void**)&xkl, g_xkl);
    cudaGetSymbolAddress((void**)&xvh, g_xvh); cudaGetSymbolAddress((void**)&xvl, g_xvl);
    cudaGetSymbolAddress((void**)&wqh, g_wqh); cudaGetSymbolAddress((void**)&wql, g_wql);
    cudaGetSymbolAddress((void**)&wkh, g_wkh); cudaGetSymbolAddress((void**)&wkl, g_wkl);
    cudaGetSymbolAddress((void**)&wvh, g_wvh); cudaGetSymbolAddress((void**)&wvl, g_wvl);
    cudaGetSymbolAddress((void**)&woh, g_woh); cudaGetSymbolAddress((void**)&wol, g_wol);
    cudaGetSymbolAddress((void**)&cxh, g_cxh); cudaGetSymbolAddress((void**)&cxl, g_cxl);
    cudaGetSymbolAddress((void**)&qh, g_qh);   cudaGetSymbolAddress((void**)&ql, g_ql);
    cudaGetSymbolAddress((void**)&kh, g_kh);   cudaGetSymbolAddress((void**)&kl, g_kl);
    cudaGetSymbolAddress((void**)&vh, g_vh);   cudaGetSymbolAddress((void**)&vl, g_vl);
    cudaGetSymbolAddress((void**)&rs, g_rs);

    const bool want_attn = ((long long)out_size >= OUT_ELEMS + ATT_ELEMS);
    float* attn = want_attn ? (out + OUT_ELEMS) : nullptr;

    // ---- 1. split fp32 inputs/weights into bf16 hi/lo planes ----
    ConvArgs ca{};
    ca.src[0] = query; ca.hi[0] = xqh; ca.lo[0] = xql; ca.n4[0] = (int)(OUT_ELEMS / 4);
    ca.src[1] = key_i; ca.hi[1] = xkh; ca.lo[1] = xkl; ca.n4[1] = (int)(OUT_ELEMS / 4);
    ca.src[2] = value; ca.hi[2] = xvh; ca.lo[2] = xvl; ca.n4[2] = (int)(OUT_ELEMS / 4);
    ca.src[3] = w_q;   ca.hi[3] = wqh; ca.lo[3] = wql; ca.n4[3] = D * D / 4;
    ca.src[4] = w_k;   ca.hi[4] = wkh; ca.lo[4] = wkl; ca.n4[4] = D * D / 4;
    ca.src[5] = w_v;   ca.hi[5] = wvh; ca.lo[5] = wvl; ca.n4[5] = D * D / 4;
    ca.src[6] = w_o;   ca.hi[6] = woh; ca.lo[6] = wol; ca.n4[6] = D * D / 4;
    convert_split<<<dim3((unsigned)(OUT_ELEMS / 4 / 256), 1, 7), 256>>>(ca);

    cudaFuncSetAttribute(gemm_bf16<1>, cudaFuncAttributeMaxDynamicSharedMemorySize, GSMEM);
    cudaFuncSetAttribute(gemm_bf16<0>, cudaFuncAttributeMaxDynamicSharedMemorySize, GSMEM);
    cudaFuncSetAttribute(pass1_vproj, cudaFuncAttributeMaxDynamicSharedMemorySize, ASMEM);
    cudaFuncSetAttribute(attn_pass2<true>, cudaFuncAttributeMaxDynamicSharedMemorySize, ASMEM);
    cudaFuncSetAttribute(attn_pass2<false>, cudaFuncAttributeMaxDynamicSharedMemorySize, ASMEM);

    GemmArgs gp{};
    gp.ah[0] = xqh; gp.al[0] = xql; gp.bh[0] = wqh; gp.bl[0] = wql;
    gp.ah[1] = xkh; gp.al[1] = xkl; gp.bh[1] = wkh; gp.bl[1] = wkl;
    gp.ah[2] = xvh; gp.al[2] = xvl; gp.bh[2] = wvh; gp.bl[2] = wvl;
    gp.chi[0] = qh; gp.clo[0] = ql;
    gp.chi[1] = kh; gp.clo[1] = kl;
    gp.chi[2] = vh; gp.clo[2] = vl;

    if (want_attn) {
        // ---- 2. Q,K projections only ----
        gemm_bf16<1><<<dim3(8, 32, 2), 256, GSMEM>>>(gp);
        // ---- 3. heterogeneous: V projection (256 tiles) + pass1 (1024) ----
        pass1_vproj<<<256 + 1024, 256, ASMEM>>>(qh, ql, kh, rs,
                                                xvh, xvl, wvh, wvl, vh, vl);
        // ---- 4. pass 2 ----
        attn_pass2<true><<<dim3(S / 64, BH), 256, ASMEM>>>(
            qh, ql, kh, kl, vh, vl, rs, cxh, cxl, attn);
    } else {
        gemm_bf16<1><<<dim3(8, 32, 3), 256, GSMEM>>>(gp);
        attn_pass2<false><<<dim3(S / 64, BH), 256, ASMEM>>>(
            qh, ql, kh, kl, vh, vl, rs, cxh, cxl, nullptr);
    }

    // ---- 5. out = ctx @ Wo^T ----
    GemmArgs go{};
    go.ah[0] = cxh; go.al[0] = cxl; go.bh[0] = woh; go.bl[0] = wol;
    go.c = out;
    gemm_bf16<0><<<dim3(8, 32, 1), 256, GSMEM>>>(go);
}

// round 16
// speedup vs baseline: 1.0588x; 1.0209x over previous
#include <cuda_runtime.h>
#include <cuda_fp16.h>
#include <stdint.h>

// ---------------------------------------------------------------------------
// MultiHeadSelfAttention: B=2, S=2048, D=1024, H=16, dk=64
// R15: hi/lo split switched bf16 -> fp16 (10-bit mantissa, same HMMA rate).
//      Precision headroom makes 1-mma pass1 SAFE (denominator err ~5e-5).
//      Structure = R14 (QK proj -> hetero Vproj+pass1 -> pass2 -> out proj).
// ---------------------------------------------------------------------------

namespace {
constexpr int BATCH = 2, S = 2048, D = 1024, H = 16, DK = 64, BH = 32;
constexpr long long OUT_ELEMS = (long long)BATCH * S * D;          // 4,194,304
constexpr long long ATT_ELEMS = (long long)BH * S * (long long)S;  // 134,217,728
constexpr int QST = 72;     // attn: Q smem stride (hi plane) fp16
constexpr int KST = 136;    // attn: K/V smem stride fp16
constexpr int GST = 40;     // gemm smem stride fp16
constexpr int NSTG = 5;     // gemm cp.async stages
constexpr int GSMEM = NSTG * 128 * GST * 2 * 2;            // 102400 B
constexpr int ASMEM = (64 * QST + 3 * 128 * KST) * 2 + 128 * 4;  // 114176 B
}

// ---- scratch (allocation-free __device__ globals) ----
__device__ __half g_xqh[(size_t)BATCH * S * D], g_xql[(size_t)BATCH * S * D];
__device__ __half g_xkh[(size_t)BATCH * S * D], g_xkl[(size_t)BATCH * S * D];
__device__ __half g_xvh[(size_t)BATCH * S * D], g_xvl[(size_t)BATCH * S * D];
__device__ __half g_wqh[(size_t)D * D], g_wql[(size_t)D * D];
__device__ __half g_wkh[(size_t)D * D], g_wkl[(size_t)D * D];
__device__ __half g_wvh[(size_t)D * D], g_wvl[(size_t)D * D];
__device__ __half g_woh[(size_t)D * D], g_wol[(size_t)D * D];
__device__ __half g_cxh[(size_t)BATCH * S * D], g_cxl[(size_t)BATCH * S * D];
__device__ __half g_qh[(size_t)BH * S * DK], g_ql[(size_t)BH * S * DK];
__device__ __half g_kh[(size_t)BH * S * DK], g_kl[(size_t)BH * S * DK];
__device__ __half g_vh[(size_t)BH * S * DK], g_vl[(size_t)BH * S * DK];
__device__ float g_rs[(size_t)BH * S];     // pass1 inverse rowsums

// ------------------------------ PTX helpers --------------------------------
__device__ __forceinline__ uint32_t smaddr(const void* p) {
    return (uint32_t)__cvta_generic_to_shared(p);
}
__device__ __forceinline__ void ldsm4(uint32_t& r0, uint32_t& r1, uint32_t& r2,
                                      uint32_t& r3, uint32_t a) {
    asm volatile("ldmatrix.sync.aligned.m8n8.x4.shared.b16 {%0,%1,%2,%3}, [%4];"
                 : "=r"(r0), "=r"(r1), "=r"(r2), "=r"(r3) : "r"(a));
}
__device__ __forceinline__ void ldsm4t(uint32_t& r0, uint32_t& r1, uint32_t& r2,
                                       uint32_t& r3, uint32_t a) {
    asm volatile("ldmatrix.sync.aligned.m8n8.x4.trans.shared.b16 {%0,%1,%2,%3}, [%4];"
                 : "=r"(r0), "=r"(r1), "=r"(r2), "=r"(r3) : "r"(a));
}
__device__ __forceinline__ void mma16816(float* c, const uint32_t* a,
                                         uint32_t b0, uint32_t b1) {
    asm volatile("mma.sync.aligned.m16n8k16.row.col.f32.f16.f16.f32 "
                 "{%0,%1,%2,%3}, {%4,%5,%6,%7}, {%8,%9}, {%0,%1,%2,%3};"
                 : "+f"(c[0]), "+f"(c[1]), "+f"(c[2]), "+f"(c[3])
                 : "r"(a[0]), "r"(a[1]), "r"(a[2]), "r"(a[3]), "r"(b0), "r"(b1));
}
__device__ __forceinline__ uint32_t packh(float a, float b) {
    __half2 t = __halves2half2(__float2half(a), __float2half(b));
    return *reinterpret_cast<uint32_t*>(&t);
}
__device__ __forceinline__ void cpa16(uint32_t dst, const void* src) {
    asm volatile("cp.async.cg.shared.global [%0], [%1], 16;" :: "r"(dst), "l"(src));
}
#define CP_COMMIT() asm volatile("cp.async.commit_group;")
#define CP_WAIT(N)  asm volatile("cp.async.wait_group %0;" :: "n"(N))

__device__ __forceinline__ void split4(const float4 f, uint2& hi, uint2& lo) {
    __half hx = __float2half(f.x), hy = __float2half(f.y);
    __half hz = __float2half(f.z), hw = __float2half(f.w);
    __half lx = __float2half(f.x - __half2float(hx));
    __half ly = __float2half(f.y - __half2float(hy));
    __half lz = __float2half(f.z - __half2float(hz));
    __half lw = __float2half(f.w - __half2float(hw));
    __half2 h01 = __halves2half2(hx, hy), h23 = __halves2half2(hz, hw);
    __half2 l01 = __halves2half2(lx, ly), l23 = __halves2half2(lz, lw);
    hi.x = *reinterpret_cast<uint32_t*>(&h01); hi.y = *reinterpret_cast<uint32_t*>(&h23);
    lo.x = *reinterpret_cast<uint32_t*>(&l01); lo.y = *reinterpret_cast<uint32_t*>(&l23);
}

// ---------------------------------------------------------------------------
// Elementwise fp32 -> fp16 hi/lo plane split. grid.z selects tensor.
// ---------------------------------------------------------------------------
struct ConvArgs {
    const float* src[8];
    __half* hi[8];
    __half* lo[8];
    int n4[8];
};

__global__ void __launch_bounds__(256)
convert_split(ConvArgs a)
{
    const int z = blockIdx.z;
    const int idx = blockIdx.x * 256 + threadIdx.x;
    if (idx >= a.n4[z]) return;
    float4 f = ((const float4*)a.src[z])[idx];
    uint2 hi, lo;
    split4(f, hi, lo);
    ((uint2*)a.hi[z])[idx] = hi;
    ((uint2*)a.lo[z])[idx] = lo;
}

// ---------------------------------------------------------------------------
// Dense NT GEMM tile body (device fn). 128x128 tile, BK=16, NSTG=5 cp.async,
// 8 warps (64x32 warp tiles), term-major 3-term hi/lo mma.
// EPI=1: fp16 hi/lo planes head-major [B,H,S,DK]; EPI=0: fp32 C row-major.
// ---------------------------------------------------------------------------
template <int EPI>
__device__ __forceinline__ void gemm_tile(
    const __half* __restrict__ Ah, const __half* __restrict__ Al,
    const __half* __restrict__ Bh, const __half* __restrict__ Bl,
    float* __restrict__ C, __half* __restrict__ Chi,
    __half* __restrict__ Clo, int m0, int n0, __half* sm)
{
    constexpr int K = 1024;
    __half* As = sm;
    __half* Bs = sm + NSTG * 128 * GST;

    const int tid = threadIdx.x, w = tid >> 5, l = tid & 31;
    const int wm = (w >> 2) * 64, wn = (w & 3) * 32;

    const int lrow = tid & 127, lpl = tid >> 7;
    const __half* srcA = (lpl ? Al : Ah) + (size_t)(m0 + lrow) * K;
    const __half* srcB = (lpl ? Bl : Bh) + (size_t)(n0 + lrow) * K;

    auto issue = [&](int kt, int stg) {
        const uint32_t da = smaddr(As + (stg * 128 + lrow) * GST + lpl * 16);
        const __half* sa = srcA + kt * 16;
        cpa16(da, sa); cpa16(da + 16, sa + 8);
        const uint32_t db = smaddr(Bs + (stg * 128 + lrow) * GST + lpl * 16);
        const __half* sb = srcB + kt * 16;
        cpa16(db, sb); cpa16(db + 16, sb + 8);
        CP_COMMIT();
    };

    const int afr = wm + (l & 15);
    const int afc = (l >> 4) * 8;
    const int bg  = l >> 3;
    const int bfr = wn + ((bg >> 1) << 3) + (l & 7);
    const int bfc = (bg & 1) * 8;

    issue(0, 0); issue(1, 1); issue(2, 2); issue(3, 3);

    float acc[4][4][4] = {};
    const int KT = K / 16;
    int stg = 0, pstg = 4;
    for (int kt = 0; kt < KT; kt++) {
        if (kt <= KT - 4)      CP_WAIT(3);
        else if (kt == KT - 3) CP_WAIT(2);
        else if (kt == KT - 2) CP_WAIT(1);
        else                   CP_WAIT(0);
        __syncthreads();
        if (kt + 4 < KT) {
            issue(kt + 4, pstg);
            if (++pstg == NSTG) pstg = 0;
        }

        const __half* AsT = As + stg * 128 * GST;
        const __half* BsT = Bs + stg * 128 * GST;
        if (++stg == NSTG) stg = 0;

        uint32_t Bhf[8], Blf[8];
        ldsm4(Bhf[0], Bhf[1], Bhf[2], Bhf[3], smaddr(&BsT[bfr * GST + bfc]));
        ldsm4(Bhf[4], Bhf[5], Bhf[6], Bhf[7], smaddr(&BsT[(bfr + 16) * GST + bfc]));
        ldsm4(Blf[0], Blf[1], Blf[2], Blf[3], smaddr(&BsT[bfr * GST + bfc + 16]));
        ldsm4(Blf[4], Blf[5], Blf[6], Blf[7], smaddr(&BsT[(bfr + 16) * GST + bfc + 16]));

        #pragma unroll
        for (int h = 0; h < 2; h++) {
            uint32_t Ahf[2][4], Alf[2][4];
            #pragma unroll
            for (int m = 0; m < 2; m++) {
                const int mf = h * 2 + m;
                ldsm4(Ahf[m][0], Ahf[m][1], Ahf[m][2], Ahf[m][3],
                      smaddr(&AsT[(afr + mf * 16) * GST + afc]));
                ldsm4(Alf[m][0], Alf[m][1], Alf[m][2], Alf[m][3],
                      smaddr(&AsT[(afr + mf * 16) * GST + afc + 16]));
            }
            #pragma unroll
            for (int m = 0; m < 2; m++)
                #pragma unroll
                for (int nf = 0; nf < 4; nf++)
                    mma16816(acc[h * 2 + m][nf], Ahf[m], Bhf[nf * 2], Bhf[nf * 2 + 1]);
            #pragma unroll
            for (int m = 0; m < 2; m++)
                #pragma unroll
                for (int nf = 0; nf < 4; nf++)
                    mma16816(acc[h * 2 + m][nf], Ahf[m], Blf[nf * 2], Blf[nf * 2 + 1]);
            #pragma unroll
            for (int m = 0; m < 2; m++)
                #pragma unroll
                for (int nf = 0; nf < 4; nf++)
                    mma16816(acc[h * 2 + m][nf], Alf[m], Bhf[nf * 2], Bhf[nf * 2 + 1]);
        }
    }

    const int er = l >> 2, ec = (l & 3) * 2;
    #pragma unroll
    for (int mf = 0; mf < 4; mf++) {
        #pragma unroll
        for (int nf = 0; nf < 4; nf++) {
            const float* c = acc[mf][nf];
            const int rr = m0 + wm + mf * 16 + er;
            const int cc = n0 + wn + nf * 8 + ec;
            if (EPI == 1) {
                const int hh = cc >> 6, dd = cc & 63;
                const int bb = rr >> 11, ss = rr & (S - 1);
                const int rr2 = rr + 8, bb2 = rr2 >> 11, ss2 = rr2 & (S - 1);
                const size_t i0 = (((size_t)bb  * H + hh) * S + ss)  * DK + dd;
                const size_t i1 = (((size_t)bb2 * H + hh) * S + ss2) * DK + dd;
                __half h0 = __float2half(c[0]), h1 = __float2half(c[1]);
                __half h2 = __float2half(c[2]), h3 = __float2half(c[3]);
                *(uint32_t*)&Chi[i0] = packh(__half2float(h0), __half2float(h1));
                *(uint32_t*)&Clo[i0] = packh(c[0] - __half2float(h0),
                                             c[1] - __half2float(h1));
                *(uint32_t*)&Chi[i1] = packh(__half2float(h2), __half2float(h3));
                *(uint32_t*)&Clo[i1] = packh(c[2] - __half2float(h2),
                                             c[3] - __half2float(h3));
            } else {
                *(float2*)&C[(size_t)rr * 1024 + cc] = make_float2(c[0], c[1]);
                *(float2*)&C[(size_t)(rr + 8) * 1024 + cc] = make_float2(c[2], c[3]);
            }
        }
    }
}

struct GemmArgs {
    const __half *ah[3], *al[3], *bh[3], *bl[3];
    float* c;
    __half *chi[3], *clo[3];
};

template <int EPI>
__global__ void __launch_bounds__(256, 2)
gemm_hf(GemmArgs ga)
{
    extern __shared__ __align__(16) __half smh[];
    const int zi = blockIdx.z;
    gemm_tile<EPI>(ga.ah[zi], ga.al[zi], ga.bh[zi], ga.bl[zi],
                   ga.c, ga.chi[zi], ga.clo[zi],
                   blockIdx.y * 128, blockIdx.x * 128, smh);
}

// ---------------------------------------------------------------------------
// Heterogeneous launch: blocks [0,256) = V projection tiles; blocks
// [256, 1280) = attention pass-1 tiles: 1-mma QK (Q-hi x K-hi; fp16 makes
// this safe), full K range, inverse rowsums written directly.
// ---------------------------------------------------------------------------
__global__ void __launch_bounds__(256, 2)
pass1_vproj(const __half* __restrict__ Qh, const __half* __restrict__ Kh,
            float* __restrict__ rs,
            const __half* __restrict__ xvh, const __half* __restrict__ xvl,
            const __half* __restrict__ wvh, const __half* __restrict__ wvl,
            __half* __restrict__ vh, __half* __restrict__ vl)
{
    extern __shared__ __align__(16) char smc[];

    if (blockIdx.x < 256) {
        const int t = blockIdx.x;
        gemm_tile<1>(xvh, xvl, wvh, wvl, nullptr, vh, vl,
                     (t >> 3) * 128, (t & 7) * 128, (__half*)smc);
        return;
    }

    __half* Qs  = (__half*)smc;
    __half* KB0 = Qs + 64 * QST;
    __half* KB1 = KB0 + 128 * KST;
    __half* Vs  = KB1 + 128 * KST;
    float* rsm = (float*)(Vs + 128 * KST);

    const int bt = blockIdx.x - 256;
    const int z = bt >> 5, y0 = (bt & 31) * 64;
    const size_t zb = (size_t)z * S * DK;

    const int tid = threadIdx.x, w = tid >> 5, l = tid & 31;
    const int wm = (w >> 1) * 16, wn = (w & 1) * 64;

    const int afr = (l & 15), afc = (l >> 4) * 8;
    const int bg = l >> 3, bRow = ((bg >> 1) << 3) + (l & 7), bc8 = (bg & 1) * 8;

    const int qrow = tid >> 2, qc = (tid & 3) * 16;
    const int krow = tid >> 1;

    if (tid < 64) rsm[tid] = 0.0f;

    // Q-hi only (1-mma pass1)
    {
        const __half* s = Qh + zb + (size_t)(y0 + qrow) * DK + qc;
        const uint32_t d = smaddr(Qs + qrow * QST + qc);
        cpa16(d, s); cpa16(d + 16, s + 8);
        CP_COMMIT();
    }

    auto issueKhi = [&](int kt, __half* dst) {
        const int hf = tid & 1;
        const __half* s = Kh + zb + (size_t)(kt * 128 + krow) * DK + hf * 32;
        const uint32_t d = smaddr(dst + krow * KST + hf * 32);
        #pragma unroll
        for (int i = 0; i < 4; i++) cpa16(d + i * 16, s + i * 8);
    };

    __half* kb[3] = { KB0, KB1, Vs };
    issueKhi(0, kb[0]); CP_COMMIT();
    issueKhi(1, kb[1]); CP_COMMIT();

    float rp0 = 0.f, rp1 = 0.f;
    for (int kt = 0; kt < 16; kt++) {
        if (kt < 15) CP_WAIT(1); else CP_WAIT(0);
        __syncthreads();
        if (kt + 2 < 16) { issueKhi(kt + 2, kb[(kt + 2) % 3]); CP_COMMIT(); }
        const __half* Kt = kb[kt % 3];
        float Sacc[8][4] = {};
        #pragma unroll
        for (int kk = 0; kk < 4; kk++) {
            uint32_t Ah[4];
            ldsm4(Ah[0], Ah[1], Ah[2], Ah[3],
                  smaddr(&Qs[(wm + afr) * QST + kk * 16 + afc]));
            #pragma unroll
            for (int g = 0; g < 4; g++) {
                uint32_t Bh[4];
                ldsm4(Bh[0], Bh[1], Bh[2], Bh[3],
                      smaddr(&Kt[(wn + g * 16 + bRow) * KST + kk * 16 + bc8]));
                mma16816(Sacc[2 * g],     Ah, Bh[0], Bh[1]);
                mma16816(Sacc[2 * g + 1], Ah, Bh[2], Bh[3]);
            }
        }
        #pragma unroll
        for (int nf = 0; nf < 8; nf++) {
            rp0 += __expf(Sacc[nf][0] * 0.125f) + __expf(Sacc[nf][1] * 0.125f);
            rp1 += __expf(Sacc[nf][2] * 0.125f) + __expf(Sacc[nf][3] * 0.125f);
        }
    }

    float v0 = rp0, v1 = rp1;
    v0 += __shfl_xor_sync(0xffffffffu, v0, 1);
    v0 += __shfl_xor_sync(0xffffffffu, v0, 2);
    v1 += __shfl_xor_sync(0xffffffffu, v1, 1);
    v1 += __shfl_xor_sync(0xffffffffu, v1, 2);
    if ((l & 3) == 0) {
        atomicAdd(&rsm[wm + (l >> 2)], v0);
        atomicAdd(&rsm[wm + (l >> 2) + 8], v1);
    }
    __syncthreads();
    if (tid < 64) rs[(size_t)z * S + y0 + tid] = 1.0f / rsm[tid];
}

// ---------------------------------------------------------------------------
// Attention pass 2. Grid (S/64, BH); 2 CTAs/SM. 3-term QK + normalized attn
// write + 3-term PV; exact local ctx norm (rsm2); ctx as fp16 hi/lo planes.
// ---------------------------------------------------------------------------
template <bool WRITE_E>
__global__ void __launch_bounds__(256, 2)
attn_pass2(const __half* __restrict__ Qh, const __half* __restrict__ Ql,
           const __half* __restrict__ Kh, const __half* __restrict__ Kl,
           const __half* __restrict__ Vh, const __half* __restrict__ Vl,
           const float* __restrict__ rs,
           __half* __restrict__ cxh, __half* __restrict__ cxl,
           float* __restrict__ attn)
{
    extern __shared__ __align__(16) char smc[];
    __half* Qs  = (__half*)smc;
    __half* KB0 = Qs + 64 * QST;
    __half* KB1 = KB0 + 128 * KST;
    __half* Vs  = KB1 + 128 * KST;
    float* rsm  = (float*)(Vs + 128 * KST);
    float* rsm2 = rsm + 64;
    float* rbuf = (float*)KB0;

    const int z = blockIdx.y, y0 = blockIdx.x * 64;
    const int bz = z >> 4, hz = z & 15;
    const size_t zb = (size_t)z * S * DK;

    const int tid = threadIdx.x, w = tid >> 5, l = tid & 31;
    const int wm = (w >> 1) * 16, wn = (w & 1) * 64;

    const int afr = (l & 15), afc = (l >> 4) * 8;
    const int bg = l >> 3, bRow = ((bg >> 1) << 3) + (l & 7), bc8 = (bg & 1) * 8;
    const int vkr = ((l >> 3) & 1) * 8 + (l & 7), vnc = (l >> 4) * 8;

    const int qrow = tid >> 2, qc = (tid & 3) * 16;
    const int krow = tid >> 1;

    if (tid < 64) rsm2[tid] = 0.0f;

    {
        const __half* s = Qh + zb + (size_t)(y0 + qrow) * DK + qc;
        const uint32_t d = smaddr(Qs + qrow * QST + qc);
        cpa16(d, s); cpa16(d + 16, s + 8);
        const __half* s2 = Ql + zb + (size_t)(y0 + qrow) * DK + qc;
        const uint32_t d2 = smaddr(Vs + qrow * KST + qc);
        cpa16(d2, s2); cpa16(d2 + 16, s2 + 8);
        CP_COMMIT();
    }
    CP_WAIT(0); __syncthreads();
    uint32_t Alr[4][4];
    #pragma unroll
    for (int kk = 0; kk < 4; kk++)
        ldsm4(Alr[kk][0], Alr[kk][1], Alr[kk][2], Alr[kk][3],
              smaddr(&Vs[(wm + afr) * KST + kk * 16 + afc]));
    __syncthreads();

    auto issueK = [&](int kt, __half* dst) {
        const int pl = tid & 1;
        const __half* s = (pl ? Kl : Kh) + zb + (size_t)(kt * 128 + krow) * DK;
        const uint32_t d = smaddr(dst + krow * KST + pl * 64);
        #pragma unroll
        for (int i = 0; i < 8; i++) cpa16(d + i * 16, s + i * 8);
    };
    auto issueV = [&](int kt) {
        const int pl = tid & 1;
        const __half* s = (pl ? Vl : Vh) + zb + (size_t)(kt * 128 + krow) * DK;
        const uint32_t d = smaddr(Vs + krow * KST + pl * 64);
        #pragma unroll
        for (int i = 0; i < 8; i++) cpa16(d + i * 16, s + i * 8);
    };

    float inv0 = 1.0f, inv1 = 1.0f;
    if (WRITE_E) {
        inv0 = rs[(size_t)z * S + y0 + wm + (l >> 2)];
        inv1 = rs[(size_t)z * S + y0 + wm + (l >> 2) + 8];
    }

    float rp0 = 0.f, rp1 = 0.f;
    float acc[8][4] = {};
    issueK(0, KB0); CP_COMMIT();
    for (int kt = 0; kt < 16; kt++) {
        CP_WAIT(0); __syncthreads();
        issueV(kt); CP_COMMIT();
        const __half* Kt = (kt & 1) ? KB1 : KB0;

        float Sacc[8][4] = {};
        #pragma unroll
        for (int kk = 0; kk < 4; kk++) {
            uint32_t Ah[4];
            ldsm4(Ah[0], Ah[1], Ah[2], Ah[3],
                  smaddr(&Qs[(wm + afr) * QST + kk * 16 + afc]));
            #pragma unroll
            for (int g = 0; g < 4; g++) {
                uint32_t Bh[4], Bl[4];
                const int row = wn + g * 16 + bRow;
                ldsm4(Bh[0], Bh[1], Bh[2], Bh[3],
                      smaddr(&Kt[row * KST + kk * 16 + bc8]));
                ldsm4(Bl[0], Bl[1], Bl[2], Bl[3],
                      smaddr(&Kt[row * KST + 64 + kk * 16 + bc8]));
                float* c0 = Sacc[2 * g];
                float* c1 = Sacc[2 * g + 1];
                mma16816(c0, Ah,      Bh[0], Bh[1]);
                mma16816(c1, Ah,      Bh[2], Bh[3]);
                mma16816(c0, Ah,      Bl[0], Bl[1]);
                mma16816(c1, Ah,      Bl[2], Bl[3]);
                mma16816(c0, Alr[kk], Bh[0], Bh[1]);
                mma16816(c1, Alr[kk], Bh[2], Bh[3]);
            }
        }
        if (kt < 15) { issueK(kt + 1, (kt & 1) ? KB0 : KB1); CP_COMMIT(); }
        if (kt < 15) CP_WAIT(1); else CP_WAIT(0);
        __syncthreads();

        #pragma unroll
        for (int j = 0; j < 4; j++) {
            uint32_t Aph[4], Apl[4];
            #pragma unroll
            for (int t = 0; t < 2; t++) {
                float* c = Sacc[2 * j + t];
                float e0 = __expf(c[0] * 0.125f), e1 = __expf(c[1] * 0.125f);
                float e2 = __expf(c[2] * 0.125f), e3 = __expf(c[3] * 0.125f);
                if (WRITE_E) { e0 *= inv0; e1 *= inv0; e2 *= inv1; e3 *= inv1; }
                rp0 += e0 + e1; rp1 += e2 + e3;
                __half h0 = __float2half(e0), h1 = __float2half(e1);
                __half h2 = __float2half(e2), h3 = __float2half(e3);
                Aph[2 * t]     = packh(__half2float(h0), __half2float(h1));
                Aph[2 * t + 1] = packh(__half2float(h2), __half2float(h3));
                Apl[2 * t]     = packh(e0 - __half2float(h0), e1 - __half2float(h1));
                Apl[2 * t + 1] = packh(e2 - __half2float(h2), e3 - __half2float(h3));
                if (WRITE_E) {
                    const int grow = y0 + wm + (l >> 2);
                    const int gcol = kt * 128 + wn + (2 * j + t) * 8 + 2 * (l & 3);
                    *(float2*)&attn[((size_t)z * S + grow) * S + gcol] = make_float2(e0, e1);
                    *(float2*)&attn[((size_t)z * S + grow + 8) * S + gcol] = make_float2(e2, e3);
                }
            }
            #pragma unroll
            for (int g = 0; g < 4; g++) {
                uint32_t Vhf[4], Vlf[4];
                const int row = wn + j * 16 + vkr;
                ldsm4t(Vhf[0], Vhf[1], Vhf[2], Vhf[3],
                       smaddr(&Vs[row * KST + g * 16 + vnc]));
                ldsm4t(Vlf[0], Vlf[1], Vlf[2], Vlf[3],
                       smaddr(&Vs[row * KST + 64 + g * 16 + vnc]));
                float* c0 = acc[2 * g];
                float* c1 = acc[2 * g + 1];
                mma16816(c0, Aph, Vhf[0], Vhf[1]);
                mma16816(c1, Aph, Vhf[2], Vhf[3]);
                mma16816(c0, Aph, Vlf[0], Vlf[1]);
                mma16816(c1, Aph, Vlf[2], Vlf[3]);
                mma16816(c0, Apl, Vhf[0], Vhf[1]);
                mma16816(c1, Apl, Vhf[2], Vhf[3]);
            }
        }
    }

    {
        float v0 = rp0, v1 = rp1;
        v0 += __shfl_xor_sync(0xffffffffu, v0, 1);
        v0 += __shfl_xor_sync(0xffffffffu, v0, 2);
        v1 += __shfl_xor_sync(0xffffffffu, v1, 1);
        v1 += __shfl_xor_sync(0xffffffffu, v1, 2);
        if ((l & 3) == 0) {
            atomicAdd(&rsm2[wm + (l >> 2)], v0);
            atomicAdd(&rsm2[wm + (l >> 2) + 8], v1);
        }
    }
    __syncthreads();
    if (tid < 64) rsm2[tid] = 1.0f / rsm2[tid];
    __syncthreads();

    const int er = l >> 2;
    if (w & 1) {
        #pragma unroll
        for (int nf = 0; nf < 8; nf++) {
            const int r = wm + er, c = nf * 8 + 2 * (l & 3);
            *(float2*)&rbuf[r * 66 + c] = make_float2(acc[nf][0], acc[nf][1]);
            *(float2*)&rbuf[(r + 8) * 66 + c] = make_float2(acc[nf][2], acc[nf][3]);
        }
    }
    __syncthreads();
    if (!(w & 1)) {
        const int r = wm + er;
        const float s0 = rsm2[r], s1 = rsm2[r + 8];
        #pragma unroll
        for (int nf = 0; nf < 8; nf++) {
            const int c = nf * 8 + 2 * (l & 3);
            float2 p0 = *(float2*)&rbuf[r * 66 + c];
            float2 p1 = *(float2*)&rbuf[(r + 8) * 66 + c];
            float o0 = (acc[nf][0] + p0.x) * s0, o1 = (acc[nf][1] + p0.y) * s0;
            float o2 = (acc[nf][2] + p1.x) * s1, o3 = (acc[nf][3] + p1.y) * s1;
            const size_t i0 = ((size_t)bz * S + y0 + r) * D + hz * 64 + c;
            const size_t i1 = ((size_t)bz * S + y0 + r + 8) * D + hz * 64 + c;
            __half h0 = __float2half(o0), h1 = __float2half(o1);
            __half h2 = __float2half(o2), h3 = __float2half(o3);
            *(uint32_t*)&cxh[i0] = packh(__half2float(h0), __half2float(h1));
            *(uint32_t*)&cxl[i0] = packh(o0 - __half2float(h0), o1 - __half2float(h1));
            *(uint32_t*)&cxh[i1] = packh(__half2float(h2), __half2float(h3));
            *(uint32_t*)&cxl[i1] = packh(o2 - __half2float(h2), o3 - __half2float(h3));
        }
    }
}

// ---------------------------------------------------------------------------
extern "C" void kernel_launch(void* const* d_in, const int* in_sizes, int n_in,
                              void* d_out, int out_size)
{
    const float* query = (const float*)d_in[0];
    const float* key_i = (const float*)d_in[1];
    const float* value = (const float*)d_in[2];
    const float* w_q   = (const float*)d_in[3];
    const float* w_k   = (const float*)d_in[4];
    const float* w_v   = (const float*)d_in[5];
    const float* w_o   = (const float*)d_in[6];
    float* out = (float*)d_out;

    __half *xqh, *xql, *xkh, *xkl, *xvh, *xvl;
    __half *wqh, *wql, *wkh, *wkl, *wvh, *wvl, *woh, *wol;
    __half *cxh, *cxl;
    __half *qh, *ql, *kh, *kl, *vh, *vl;
    float *rs;
    cudaGetSymbolAddress((void**)&xqh, g_xqh); cudaGetSymbolAddress((void**)&xql, g_xql);
    cudaGetSymbolAddress((void**)&xkh, g_xkh); cudaGetSymbolAddress((void**)&xkl, g_xkl);
    cudaGetSymbolAddress((void**)&xvh, g_xvh); cudaGetSymbolAddress((void**)&xvl, g_xvl);
    cudaGetSymbolAddress((void**)&wqh, g_wqh); cudaGetSymbolAddress((void**)&wql, g_wql);
    cudaGetSymbolAddress((void**)&wkh, g_wkh); cudaGetSymbolAddress((void**)&wkl, g_wkl);
    cudaGetSymbolAddress((void**)&wvh, g_wvh); cudaGetSymbolAddress((void**)&wvl, g_wvl);
    cudaGetSymbolAddress((void**)&woh, g_woh); cudaGetSymbolAddress((void**)&wol, g_wol);
    cudaGetSymbolAddress((void**)&cxh, g_cxh); cudaGetSymbolAddress((void**)&cxl, g_cxl);
    cudaGetSymbolAddress((void**)&qh, g_qh);   cudaGetSymbolAddress((void**)&ql, g_ql);
    cudaGetSymbolAddress((void**)&kh, g_kh);   cudaGetSymbolAddress((void**)&kl, g_kl);
    cudaGetSymbolAddress((void**)&vh, g_vh);   cudaGetSymbolAddress((void**)&vl, g_vl);
    cudaGetSymbolAddress((void**)&rs, g_rs);

    const bool want_attn = ((long long)out_size >= OUT_ELEMS + ATT_ELEMS);
    float* attn = want_attn ? (out + OUT_ELEMS) : nullptr;

    // ---- 1. split fp32 inputs/weights into fp16 hi/lo planes ----
    ConvArgs ca{};
    ca.src[0] = query; ca.hi[0] = xqh; ca.lo[0] = xql; ca.n4[0] = (int)(OUT_ELEMS / 4);
    ca.src[1] = key_i; ca.hi[1] = xkh; ca.lo[1] = xkl; ca.n4[1] = (int)(OUT_ELEMS / 4);
    ca.src[2] = value; ca.hi[2] = xvh; ca.lo[2] = xvl; ca.n4[2] = (int)(OUT_ELEMS / 4);
    ca.src[3] = w_q;   ca.hi[3] = wqh; ca.lo[3] = wql; ca.n4[3] = D * D / 4;
    ca.src[4] = w_k;   ca.hi[4] = wkh; ca.lo[4] = wkl; ca.n4[4] = D * D / 4;
    ca.src[5] = w_v;   ca.hi[5] = wvh; ca.lo[5] = wvl; ca.n4[5] = D * D / 4;
    ca.src[6] = w_o;   ca.hi[6] = woh; ca.lo[6] = wol; ca.n4[6] = D * D / 4;
    convert_split<<<dim3((unsigned)(OUT_ELEMS / 4 / 256), 1, 7), 256>>>(ca);

    cudaFuncSetAttribute(gemm_hf<1>, cudaFuncAttributeMaxDynamicSharedMemorySize, GSMEM);
    cudaFuncSetAttribute(gemm_hf<0>, cudaFuncAttributeMaxDynamicSharedMemorySize, GSMEM);
    cudaFuncSetAttribute(pass1_vproj, cudaFuncAttributeMaxDynamicSharedMemorySize, ASMEM);
    cudaFuncSetAttribute(attn_pass2<true>, cudaFuncAttributeMaxDynamicSharedMemorySize, ASMEM);
    cudaFuncSetAttribute(attn_pass2<false>, cudaFuncAttributeMaxDynamicSharedMemorySize, ASMEM);

    GemmArgs gp{};
    gp.ah[0] = xqh; gp.al[0] = xql; gp.bh[0] = wqh; gp.bl[0] = wql;
    gp.ah[1] = xkh; gp.al[1] = xkl; gp.bh[1] = wkh; gp.bl[1] = wkl;
    gp.ah[2] = xvh; gp.al[2] = xvl; gp.bh[2] = wvh; gp.bl[2] = wvl;
    gp.chi[0] = qh; gp.clo[0] = ql;
    gp.chi[1] = kh; gp.clo[1] = kl;
    gp.chi[2] = vh; gp.clo[2] = vl;

    if (want_attn) {
        // ---- 2. Q,K projections ----
        gemm_hf<1><<<dim3(8, 32, 2), 256, GSMEM>>>(gp);
        // ---- 3. heterogeneous: V projection (256) + pass1 1-mma (1024) ----
        pass1_vproj<<<256 + 1024, 256, ASMEM>>>(qh, kh, rs,
                                                xvh, xvl, wvh, wvl, vh, vl);
        // ---- 4. pass 2 ----
        attn_pass2<true><<<dim3(S / 64, BH), 256, ASMEM>>>(
            qh, ql, kh, kl, vh, vl, rs, cxh, cxl, attn);
    } else {
        gemm_hf<1><<<dim3(8, 32, 3), 256, GSMEM>>>(gp);
        attn_pass2<false><<<dim3(S / 64, BH), 256, ASMEM>>>(
            qh, ql, kh, kl, vh, vl, rs, cxh, cxl, nullptr);
    }

    // ---- 5. out = ctx @ Wo^T ----
    GemmArgs go{};
    go.ah[0] = cxh; go.al[0] = cxl; go.bh[0] = woh; go.bl[0] = wol;
    go.c = out;
    gemm_hf<0><<<dim3(8, 32, 1), 256, GSMEM>>>(go);
}

// round 17
// speedup vs baseline: 1.1860x; 1.1201x over previous
#include <cuda_runtime.h>
#include <cuda_fp16.h>
#include <stdint.h>

// ---------------------------------------------------------------------------
// MultiHeadSelfAttention: B=2, S=2048, D=1024, H=16, dk=64
// R16: pass2 QK reduced to 2-term (Qhi*Khi + Qlo*Khi); K-lo never loaded in
//      pass2 (hi-plane cp.async only). fp16 error model (validated R15->R16)
//      predicts rel_err ~2.9e-4 (3.4x margin). Rest = R15 structure.
// ---------------------------------------------------------------------------

namespace {
constexpr int BATCH = 2, S = 2048, D = 1024, H = 16, DK = 64, BH = 32;
constexpr long long OUT_ELEMS = (long long)BATCH * S * D;          // 4,194,304
constexpr long long ATT_ELEMS = (long long)BH * S * (long long)S;  // 134,217,728
constexpr int QST = 72;     // attn: Q smem stride (hi plane) fp16
constexpr int KST = 136;    // attn: K/V smem stride fp16
constexpr int GST = 40;     // gemm smem stride fp16
constexpr int NSTG = 5;     // gemm cp.async stages
constexpr int GSMEM = NSTG * 128 * GST * 2 * 2;            // 102400 B
constexpr int ASMEM = (64 * QST + 3 * 128 * KST) * 2 + 128 * 4;  // 114176 B
}

// ---- scratch (allocation-free __device__ globals) ----
__device__ __half g_xqh[(size_t)BATCH * S * D], g_xql[(size_t)BATCH * S * D];
__device__ __half g_xkh[(size_t)BATCH * S * D], g_xkl[(size_t)BATCH * S * D];
__device__ __half g_xvh[(size_t)BATCH * S * D], g_xvl[(size_t)BATCH * S * D];
__device__ __half g_wqh[(size_t)D * D], g_wql[(size_t)D * D];
__device__ __half g_wkh[(size_t)D * D], g_wkl[(size_t)D * D];
__device__ __half g_wvh[(size_t)D * D], g_wvl[(size_t)D * D];
__device__ __half g_woh[(size_t)D * D], g_wol[(size_t)D * D];
__device__ __half g_cxh[(size_t)BATCH * S * D], g_cxl[(size_t)BATCH * S * D];
__device__ __half g_qh[(size_t)BH * S * DK], g_ql[(size_t)BH * S * DK];
__device__ __half g_kh[(size_t)BH * S * DK], g_kl[(size_t)BH * S * DK];
__device__ __half g_vh[(size_t)BH * S * DK], g_vl[(size_t)BH * S * DK];
__device__ float g_rs[(size_t)BH * S];     // pass1 inverse rowsums

// ------------------------------ PTX helpers --------------------------------
__device__ __forceinline__ uint32_t smaddr(const void* p) {
    return (uint32_t)__cvta_generic_to_shared(p);
}
__device__ __forceinline__ void ldsm4(uint32_t& r0, uint32_t& r1, uint32_t& r2,
                                      uint32_t& r3, uint32_t a) {
    asm volatile("ldmatrix.sync.aligned.m8n8.x4.shared.b16 {%0,%1,%2,%3}, [%4];"
                 : "=r"(r0), "=r"(r1), "=r"(r2), "=r"(r3) : "r"(a));
}
__device__ __forceinline__ void ldsm4t(uint32_t& r0, uint32_t& r1, uint32_t& r2,
                                       uint32_t& r3, uint32_t a) {
    asm volatile("ldmatrix.sync.aligned.m8n8.x4.trans.shared.b16 {%0,%1,%2,%3}, [%4];"
                 : "=r"(r0), "=r"(r1), "=r"(r2), "=r"(r3) : "r"(a));
}
__device__ __forceinline__ void mma16816(float* c, const uint32_t* a,
                                         uint32_t b0, uint32_t b1) {
    asm volatile("mma.sync.aligned.m16n8k16.row.col.f32.f16.f16.f32 "
                 "{%0,%1,%2,%3}, {%4,%5,%6,%7}, {%8,%9}, {%0,%1,%2,%3};"
                 : "+f"(c[0]), "+f"(c[1]), "+f"(c[2]), "+f"(c[3])
                 : "r"(a[0]), "r"(a[1]), "r"(a[2]), "r"(a[3]), "r"(b0), "r"(b1));
}
__device__ __forceinline__ uint32_t packh(float a, float b) {
    __half2 t = __halves2half2(__float2half(a), __float2half(b));
    return *reinterpret_cast<uint32_t*>(&t);
}
__device__ __forceinline__ void cpa16(uint32_t dst, const void* src) {
    asm volatile("cp.async.cg.shared.global [%0], [%1], 16;" :: "r"(dst), "l"(src));
}
#define CP_COMMIT() asm volatile("cp.async.commit_group;")
#define CP_WAIT(N)  asm volatile("cp.async.wait_group %0;" :: "n"(N))

__device__ __forceinline__ void split4(const float4 f, uint2& hi, uint2& lo) {
    __half hx = __float2half(f.x), hy = __float2half(f.y);
    __half hz = __float2half(f.z), hw = __float2half(f.w);
    __half lx = __float2half(f.x - __half2float(hx));
    __half ly = __float2half(f.y - __half2float(hy));
    __half lz = __float2half(f.z - __half2float(hz));
    __half lw = __float2half(f.w - __half2float(hw));
    __half2 h01 = __halves2half2(hx, hy), h23 = __halves2half2(hz, hw);
    __half2 l01 = __halves2half2(lx, ly), l23 = __halves2half2(lz, lw);
    hi.x = *reinterpret_cast<uint32_t*>(&h01); hi.y = *reinterpret_cast<uint32_t*>(&h23);
    lo.x = *reinterpret_cast<uint32_t*>(&l01); lo.y = *reinterpret_cast<uint32_t*>(&l23);
}

// ---------------------------------------------------------------------------
// Elementwise fp32 -> fp16 hi/lo plane split. grid.z selects tensor.
// ---------------------------------------------------------------------------
struct ConvArgs {
    const float* src[8];
    __half* hi[8];
    __half* lo[8];
    int n4[8];
};

__global__ void __launch_bounds__(256)
convert_split(ConvArgs a)
{
    const int z = blockIdx.z;
    const int idx = blockIdx.x * 256 + threadIdx.x;
    if (idx >= a.n4[z]) return;
    float4 f = ((const float4*)a.src[z])[idx];
    uint2 hi, lo;
    split4(f, hi, lo);
    ((uint2*)a.hi[z])[idx] = hi;
    ((uint2*)a.lo[z])[idx] = lo;
}

// ---------------------------------------------------------------------------
// Dense NT GEMM tile body (device fn). 128x128 tile, BK=16, NSTG=5 cp.async,
// 8 warps (64x32 warp tiles), term-major 3-term hi/lo mma.
// EPI=1: fp16 hi/lo planes head-major [B,H,S,DK]; EPI=0: fp32 C row-major.
// ---------------------------------------------------------------------------
template <int EPI>
__device__ __forceinline__ void gemm_tile(
    const __half* __restrict__ Ah, const __half* __restrict__ Al,
    const __half* __restrict__ Bh, const __half* __restrict__ Bl,
    float* __restrict__ C, __half* __restrict__ Chi,
    __half* __restrict__ Clo, int m0, int n0, __half* sm)
{
    constexpr int K = 1024;
    __half* As = sm;
    __half* Bs = sm + NSTG * 128 * GST;

    const int tid = threadIdx.x, w = tid >> 5, l = tid & 31;
    const int wm = (w >> 2) * 64, wn = (w & 3) * 32;

    const int lrow = tid & 127, lpl = tid >> 7;
    const __half* srcA = (lpl ? Al : Ah) + (size_t)(m0 + lrow) * K;
    const __half* srcB = (lpl ? Bl : Bh) + (size_t)(n0 + lrow) * K;

    auto issue = [&](int kt, int stg) {
        const uint32_t da = smaddr(As + (stg * 128 + lrow) * GST + lpl * 16);
        const __half* sa = srcA + kt * 16;
        cpa16(da, sa); cpa16(da + 16, sa + 8);
        const uint32_t db = smaddr(Bs + (stg * 128 + lrow) * GST + lpl * 16);
        const __half* sb = srcB + kt * 16;
        cpa16(db, sb); cpa16(db + 16, sb + 8);
        CP_COMMIT();
    };

    const int afr = wm + (l & 15);
    const int afc = (l >> 4) * 8;
    const int bg  = l >> 3;
    const int bfr = wn + ((bg >> 1) << 3) + (l & 7);
    const int bfc = (bg & 1) * 8;

    issue(0, 0); issue(1, 1); issue(2, 2); issue(3, 3);

    float acc[4][4][4] = {};
    const int KT = K / 16;
    int stg = 0, pstg = 4;
    for (int kt = 0; kt < KT; kt++) {
        if (kt <= KT - 4)      CP_WAIT(3);
        else if (kt == KT - 3) CP_WAIT(2);
        else if (kt == KT - 2) CP_WAIT(1);
        else                   CP_WAIT(0);
        __syncthreads();
        if (kt + 4 < KT) {
            issue(kt + 4, pstg);
            if (++pstg == NSTG) pstg = 0;
        }

        const __half* AsT = As + stg * 128 * GST;
        const __half* BsT = Bs + stg * 128 * GST;
        if (++stg == NSTG) stg = 0;

        uint32_t Bhf[8], Blf[8];
        ldsm4(Bhf[0], Bhf[1], Bhf[2], Bhf[3], smaddr(&BsT[bfr * GST + bfc]));
        ldsm4(Bhf[4], Bhf[5], Bhf[6], Bhf[7], smaddr(&BsT[(bfr + 16) * GST + bfc]));
        ldsm4(Blf[0], Blf[1], Blf[2], Blf[3], smaddr(&BsT[bfr * GST + bfc + 16]));
        ldsm4(Blf[4], Blf[5], Blf[6], Blf[7], smaddr(&BsT[(bfr + 16) * GST + bfc + 16]));

        #pragma unroll
        for (int h = 0; h < 2; h++) {
            uint32_t Ahf[2][4], Alf[2][4];
            #pragma unroll
            for (int m = 0; m < 2; m++) {
                const int mf = h * 2 + m;
                ldsm4(Ahf[m][0], Ahf[m][1], Ahf[m][2], Ahf[m][3],
                      smaddr(&AsT[(afr + mf * 16) * GST + afc]));
                ldsm4(Alf[m][0], Alf[m][1], Alf[m][2], Alf[m][3],
                      smaddr(&AsT[(afr + mf * 16) * GST + afc + 16]));
            }
            #pragma unroll
            for (int m = 0; m < 2; m++)
                #pragma unroll
                for (int nf = 0; nf < 4; nf++)
                    mma16816(acc[h * 2 + m][nf], Ahf[m], Bhf[nf * 2], Bhf[nf * 2 + 1]);
            #pragma unroll
            for (int m = 0; m < 2; m++)
                #pragma unroll
                for (int nf = 0; nf < 4; nf++)
                    mma16816(acc[h * 2 + m][nf], Ahf[m], Blf[nf * 2], Blf[nf * 2 + 1]);
            #pragma unroll
            for (int m = 0; m < 2; m++)
                #pragma unroll
                for (int nf = 0; nf < 4; nf++)
                    mma16816(acc[h * 2 + m][nf], Alf[m], Bhf[nf * 2], Bhf[nf * 2 + 1]);
        }
    }

    const int er = l >> 2, ec = (l & 3) * 2;
    #pragma unroll
    for (int mf = 0; mf < 4; mf++) {
        #pragma unroll
        for (int nf = 0; nf < 4; nf++) {
            const float* c = acc[mf][nf];
            const int rr = m0 + wm + mf * 16 + er;
            const int cc = n0 + wn + nf * 8 + ec;
            if (EPI == 1) {
                const int hh = cc >> 6, dd = cc & 63;
                const int bb = rr >> 11, ss = rr & (S - 1);
                const int rr2 = rr + 8, bb2 = rr2 >> 11, ss2 = rr2 & (S - 1);
                const size_t i0 = (((size_t)bb  * H + hh) * S + ss)  * DK + dd;
                const size_t i1 = (((size_t)bb2 * H + hh) * S + ss2) * DK + dd;
                __half h0 = __float2half(c[0]), h1 = __float2half(c[1]);
                __half h2 = __float2half(c[2]), h3 = __float2half(c[3]);
                *(uint32_t*)&Chi[i0] = packh(__half2float(h0), __half2float(h1));
                *(uint32_t*)&Clo[i0] = packh(c[0] - __half2float(h0),
                                             c[1] - __half2float(h1));
                *(uint32_t*)&Chi[i1] = packh(__half2float(h2), __half2float(h3));
                *(uint32_t*)&Clo[i1] = packh(c[2] - __half2float(h2),
                                             c[3] - __half2float(h3));
            } else {
                *(float2*)&C[(size_t)rr * 1024 + cc] = make_float2(c[0], c[1]);
                *(float2*)&C[(size_t)(rr + 8) * 1024 + cc] = make_float2(c[2], c[3]);
            }
        }
    }
}

struct GemmArgs {
    const __half *ah[3], *al[3], *bh[3], *bl[3];
    float* c;
    __half *chi[3], *clo[3];
};

template <int EPI>
__global__ void __launch_bounds__(256, 2)
gemm_hf(GemmArgs ga)
{
    extern __shared__ __align__(16) __half smh[];
    const int zi = blockIdx.z;
    gemm_tile<EPI>(ga.ah[zi], ga.al[zi], ga.bh[zi], ga.bl[zi],
                   ga.c, ga.chi[zi], ga.clo[zi],
                   blockIdx.y * 128, blockIdx.x * 128, smh);
}

// ---------------------------------------------------------------------------
// Heterogeneous launch: blocks [0,256) = V projection tiles; blocks
// [256, 1280) = attention pass-1 tiles (1-mma QK, inverse rowsums direct).
// ---------------------------------------------------------------------------
__global__ void __launch_bounds__(256, 2)
pass1_vproj(const __half* __restrict__ Qh, const __half* __restrict__ Kh,
            float* __restrict__ rs,
            const __half* __restrict__ xvh, const __half* __restrict__ xvl,
            const __half* __restrict__ wvh, const __half* __restrict__ wvl,
            __half* __restrict__ vh, __half* __restrict__ vl)
{
    extern __shared__ __align__(16) char smc[];

    if (blockIdx.x < 256) {
        const int t = blockIdx.x;
        gemm_tile<1>(xvh, xvl, wvh, wvl, nullptr, vh, vl,
                     (t >> 3) * 128, (t & 7) * 128, (__half*)smc);
        return;
    }

    __half* Qs  = (__half*)smc;
    __half* KB0 = Qs + 64 * QST;
    __half* KB1 = KB0 + 128 * KST;
    __half* Vs  = KB1 + 128 * KST;
    float* rsm = (float*)(Vs + 128 * KST);

    const int bt = blockIdx.x - 256;
    const int z = bt >> 5, y0 = (bt & 31) * 64;
    const size_t zb = (size_t)z * S * DK;

    const int tid = threadIdx.x, w = tid >> 5, l = tid & 31;
    const int wm = (w >> 1) * 16, wn = (w & 1) * 64;

    const int afr = (l & 15), afc = (l >> 4) * 8;
    const int bg = l >> 3, bRow = ((bg >> 1) << 3) + (l & 7), bc8 = (bg & 1) * 8;

    const int qrow = tid >> 2, qc = (tid & 3) * 16;
    const int krow = tid >> 1;

    if (tid < 64) rsm[tid] = 0.0f;

    {
        const __half* s = Qh + zb + (size_t)(y0 + qrow) * DK + qc;
        const uint32_t d = smaddr(Qs + qrow * QST + qc);
        cpa16(d, s); cpa16(d + 16, s + 8);
        CP_COMMIT();
    }

    auto issueKhi = [&](int kt, __half* dst) {
        const int hf = tid & 1;
        const __half* s = Kh + zb + (size_t)(kt * 128 + krow) * DK + hf * 32;
        const uint32_t d = smaddr(dst + krow * KST + hf * 32);
        #pragma unroll
        for (int i = 0; i < 4; i++) cpa16(d + i * 16, s + i * 8);
    };

    __half* kb[3] = { KB0, KB1, Vs };
    issueKhi(0, kb[0]); CP_COMMIT();
    issueKhi(1, kb[1]); CP_COMMIT();

    float rp0 = 0.f, rp1 = 0.f;
    for (int kt = 0; kt < 16; kt++) {
        if (kt < 15) CP_WAIT(1); else CP_WAIT(0);
        __syncthreads();
        if (kt + 2 < 16) { issueKhi(kt + 2, kb[(kt + 2) % 3]); CP_COMMIT(); }
        const __half* Kt = kb[kt % 3];
        float Sacc[8][4] = {};
        #pragma unroll
        for (int kk = 0; kk < 4; kk++) {
            uint32_t Ah[4];
            ldsm4(Ah[0], Ah[1], Ah[2], Ah[3],
                  smaddr(&Qs[(wm + afr) * QST + kk * 16 + afc]));
            #pragma unroll
            for (int g = 0; g < 4; g++) {
                uint32_t Bh[4];
                ldsm4(Bh[0], Bh[1], Bh[2], Bh[3],
                      smaddr(&Kt[(wn + g * 16 + bRow) * KST + kk * 16 + bc8]));
                mma16816(Sacc[2 * g],     Ah, Bh[0], Bh[1]);
                mma16816(Sacc[2 * g + 1], Ah, Bh[2], Bh[3]);
            }
        }
        #pragma unroll
        for (int nf = 0; nf < 8; nf++) {
            rp0 += __expf(Sacc[nf][0] * 0.125f) + __expf(Sacc[nf][1] * 0.125f);
            rp1 += __expf(Sacc[nf][2] * 0.125f) + __expf(Sacc[nf][3] * 0.125f);
        }
    }

    float v0 = rp0, v1 = rp1;
    v0 += __shfl_xor_sync(0xffffffffu, v0, 1);
    v0 += __shfl_xor_sync(0xffffffffu, v0, 2);
    v1 += __shfl_xor_sync(0xffffffffu, v1, 1);
    v1 += __shfl_xor_sync(0xffffffffu, v1, 2);
    if ((l & 3) == 0) {
        atomicAdd(&rsm[wm + (l >> 2)], v0);
        atomicAdd(&rsm[wm + (l >> 2) + 8], v1);
    }
    __syncthreads();
    if (tid < 64) rs[(size_t)z * S + y0 + tid] = 1.0f / rsm[tid];
}

// ---------------------------------------------------------------------------
// Attention pass 2. Grid (S/64, BH); 2 CTAs/SM. 2-term QK (Qhi*Khi+Qlo*Khi,
// K-lo never loaded) + normalized attn write + 3-term PV; exact local ctx
// norm (rsm2); ctx as fp16 hi/lo planes.
// ---------------------------------------------------------------------------
template <bool WRITE_E>
__global__ void __launch_bounds__(256, 2)
attn_pass2(const __half* __restrict__ Qh, const __half* __restrict__ Ql,
           const __half* __restrict__ Kh,
           const __half* __restrict__ Vh, const __half* __restrict__ Vl,
           const float* __restrict__ rs,
           __half* __restrict__ cxh, __half* __restrict__ cxl,
           float* __restrict__ attn)
{
    extern __shared__ __align__(16) char smc[];
    __half* Qs  = (__half*)smc;
    __half* KB0 = Qs + 64 * QST;
    __half* KB1 = KB0 + 128 * KST;
    __half* Vs  = KB1 + 128 * KST;
    float* rsm  = (float*)(Vs + 128 * KST);
    float* rsm2 = rsm + 64;
    float* rbuf = (float*)KB0;

    const int z = blockIdx.y, y0 = blockIdx.x * 64;
    const int bz = z >> 4, hz = z & 15;
    const size_t zb = (size_t)z * S * DK;

    const int tid = threadIdx.x, w = tid >> 5, l = tid & 31;
    const int wm = (w >> 1) * 16, wn = (w & 1) * 64;

    const int afr = (l & 15), afc = (l >> 4) * 8;
    const int bg = l >> 3, bRow = ((bg >> 1) << 3) + (l & 7), bc8 = (bg & 1) * 8;
    const int vkr = ((l >> 3) & 1) * 8 + (l & 7), vnc = (l >> 4) * 8;

    const int qrow = tid >> 2, qc = (tid & 3) * 16;
    const int krow = tid >> 1;

    if (tid < 64) rsm2[tid] = 0.0f;

    {
        const __half* s = Qh + zb + (size_t)(y0 + qrow) * DK + qc;
        const uint32_t d = smaddr(Qs + qrow * QST + qc);
        cpa16(d, s); cpa16(d + 16, s + 8);
        const __half* s2 = Ql + zb + (size_t)(y0 + qrow) * DK + qc;
        const uint32_t d2 = smaddr(Vs + qrow * KST + qc);
        cpa16(d2, s2); cpa16(d2 + 16, s2 + 8);
        CP_COMMIT();
    }
    CP_WAIT(0); __syncthreads();
    uint32_t Alr[4][4];
    #pragma unroll
    for (int kk = 0; kk < 4; kk++)
        ldsm4(Alr[kk][0], Alr[kk][1], Alr[kk][2], Alr[kk][3],
              smaddr(&Vs[(wm + afr) * KST + kk * 16 + afc]));
    __syncthreads();

    // K: hi plane only (2-term QK)
    auto issueK = [&](int kt, __half* dst) {
        const int hf = tid & 1;
        const __half* s = Kh + zb + (size_t)(kt * 128 + krow) * DK + hf * 32;
        const uint32_t d = smaddr(dst + krow * KST + hf * 32);
        #pragma unroll
        for (int i = 0; i < 4; i++) cpa16(d + i * 16, s + i * 8);
    };
    auto issueV = [&](int kt) {
        const int pl = tid & 1;
        const __half* s = (pl ? Vl : Vh) + zb + (size_t)(kt * 128 + krow) * DK;
        const uint32_t d = smaddr(Vs + krow * KST + pl * 64);
        #pragma unroll
        for (int i = 0; i < 8; i++) cpa16(d + i * 16, s + i * 8);
    };

    float inv0 = 1.0f, inv1 = 1.0f;
    if (WRITE_E) {
        inv0 = rs[(size_t)z * S + y0 + wm + (l >> 2)];
        inv1 = rs[(size_t)z * S + y0 + wm + (l >> 2) + 8];
    }

    float rp0 = 0.f, rp1 = 0.f;
    float acc[8][4] = {};
    issueK(0, KB0); CP_COMMIT();
    for (int kt = 0; kt < 16; kt++) {
        CP_WAIT(0); __syncthreads();
        issueV(kt); CP_COMMIT();
        const __half* Kt = (kt & 1) ? KB1 : KB0;

        float Sacc[8][4] = {};
        #pragma unroll
        for (int kk = 0; kk < 4; kk++) {
            uint32_t Ah[4];
            ldsm4(Ah[0], Ah[1], Ah[2], Ah[3],
                  smaddr(&Qs[(wm + afr) * QST + kk * 16 + afc]));
            #pragma unroll
            for (int g = 0; g < 4; g++) {
                uint32_t Bh[4];
                const int row = wn + g * 16 + bRow;
                ldsm4(Bh[0], Bh[1], Bh[2], Bh[3],
                      smaddr(&Kt[row * KST + kk * 16 + bc8]));
                float* c0 = Sacc[2 * g];
                float* c1 = Sacc[2 * g + 1];
                mma16816(c0, Ah,      Bh[0], Bh[1]);
                mma16816(c1, Ah,      Bh[2], Bh[3]);
                mma16816(c0, Alr[kk], Bh[0], Bh[1]);
                mma16816(c1, Alr[kk], Bh[2], Bh[3]);
            }
        }
        if (kt < 15) { issueK(kt + 1, (kt & 1) ? KB0 : KB1); CP_COMMIT(); }
        if (kt < 15) CP_WAIT(1); else CP_WAIT(0);
        __syncthreads();

        #pragma unroll
        for (int j = 0; j < 4; j++) {
            uint32_t Aph[4], Apl[4];
            #pragma unroll
            for (int t = 0; t < 2; t++) {
                float* c = Sacc[2 * j + t];
                float e0 = __expf(c[0] * 0.125f), e1 = __expf(c[1] * 0.125f);
                float e2 = __expf(c[2] * 0.125f), e3 = __expf(c[3] * 0.125f);
                if (WRITE_E) { e0 *= inv0; e1 *= inv0; e2 *= inv1; e3 *= inv1; }
                rp0 += e0 + e1; rp1 += e2 + e3;
                __half h0 = __float2half(e0), h1 = __float2half(e1);
                __half h2 = __float2half(e2), h3 = __float2half(e3);
                Aph[2 * t]     = packh(__half2float(h0), __half2float(h1));
                Aph[2 * t + 1] = packh(__half2float(h2), __half2float(h3));
                Apl[2 * t]     = packh(e0 - __half2float(h0), e1 - __half2float(h1));
                Apl[2 * t + 1] = packh(e2 - __half2float(h2), e3 - __half2float(h3));
                if (WRITE_E) {
                    const int grow = y0 + wm + (l >> 2);
                    const int gcol = kt * 128 + wn + (2 * j + t) * 8 + 2 * (l & 3);
                    *(float2*)&attn[((size_t)z * S + grow) * S + gcol] = make_float2(e0, e1);
                    *(float2*)&attn[((size_t)z * S + grow + 8) * S + gcol] = make_float2(e2, e3);
                }
            }
            #pragma unroll
            for (int g = 0; g < 4; g++) {
                uint32_t Vhf[4], Vlf[4];
                const int row = wn + j * 16 + vkr;
                ldsm4t(Vhf[0], Vhf[1], Vhf[2], Vhf[3],
                       smaddr(&Vs[row * KST + g * 16 + vnc]));
                ldsm4t(Vlf[0], Vlf[1], Vlf[2], Vlf[3],
                       smaddr(&Vs[row * KST + 64 + g * 16 + vnc]));
                float* c0 = acc[2 * g];
                float* c1 = acc[2 * g + 1];
                mma16816(c0, Aph, Vhf[0], Vhf[1]);
                mma16816(c1, Aph, Vhf[2], Vhf[3]);
                mma16816(c0, Aph, Vlf[0], Vlf[1]);
                mma16816(c1, Aph, Vlf[2], Vlf[3]);
                mma16816(c0, Apl, Vhf[0], Vhf[1]);
                mma16816(c1, Apl, Vhf[2], Vhf[3]);
            }
        }
    }

    {
        float v0 = rp0, v1 = rp1;
        v0 += __shfl_xor_sync(0xffffffffu, v0, 1);
        v0 += __shfl_xor_sync(0xffffffffu, v0, 2);
        v1 += __shfl_xor_sync(0xffffffffu, v1, 1);
        v1 += __shfl_xor_sync(0xffffffffu, v1, 2);
        if ((l & 3) == 0) {
            atomicAdd(&rsm2[wm + (l >> 2)], v0);
            atomicAdd(&rsm2[wm + (l >> 2) + 8], v1);
        }
    }
    __syncthreads();
    if (tid < 64) rsm2[tid] = 1.0f / rsm2[tid];
    __syncthreads();

    const int er = l >> 2;
    if (w & 1) {
        #pragma unroll
        for (int nf = 0; nf < 8; nf++) {
            const int r = wm + er, c = nf * 8 + 2 * (l & 3);
            *(float2*)&rbuf[r * 66 + c] = make_float2(acc[nf][0], acc[nf][1]);
            *(float2*)&rbuf[(r + 8) * 66 + c] = make_float2(acc[nf][2], acc[nf][3]);
        }
    }
    __syncthreads();
    if (!(w & 1)) {
        const int r = wm + er;
        const float s0 = rsm2[r], s1 = rsm2[r + 8];
        #pragma unroll
        for (int nf = 0; nf < 8; nf++) {
            const int c = nf * 8 + 2 * (l & 3);
            float2 p0 = *(float2*)&rbuf[r * 66 + c];
            float2 p1 = *(float2*)&rbuf[(r + 8) * 66 + c];
            float o0 = (acc[nf][0] + p0.x) * s0, o1 = (acc[nf][1] + p0.y) * s0;
            float o2 = (acc[nf][2] + p1.x) * s1, o3 = (acc[nf][3] + p1.y) * s1;
            const size_t i0 = ((size_t)bz * S + y0 + r) * D + hz * 64 + c;
            const size_t i1 = ((size_t)bz * S + y0 + r + 8) * D + hz * 64 + c;
            __half h0 = __float2half(o0), h1 = __float2half(o1);
            __half h2 = __float2half(o2), h3 = __float2half(o3);
            *(uint32_t*)&cxh[i0] = packh(__half2float(h0), __half2float(h1));
            *(uint32_t*)&cxl[i0] = packh(o0 - __half2float(h0), o1 - __half2float(h1));
            *(uint32_t*)&cxh[i1] = packh(__half2float(h2), __half2float(h3));
            *(uint32_t*)&cxl[i1] = packh(o2 - __half2float(h2), o3 - __half2float(h3));
        }
    }
}

// ---------------------------------------------------------------------------
extern "C" void kernel_launch(void* const* d_in, const int* in_sizes, int n_in,
                              void* d_out, int out_size)
{
    const float* query = (const float*)d_in[0];
    const float* key_i = (const float*)d_in[1];
    const float* value = (const float*)d_in[2];
    const float* w_q   = (const float*)d_in[3];
    const float* w_k   = (const float*)d_in[4];
    const float* w_v   = (const float*)d_in[5];
    const float* w_o   = (const float*)d_in[6];
    float* out = (float*)d_out;

    __half *xqh, *xql, *xkh, *xkl, *xvh, *xvl;
    __half *wqh, *wql, *wkh, *wkl, *wvh, *wvl, *woh, *wol;
    __half *cxh, *cxl;
    __half *qh, *ql, *kh, *kl, *vh, *vl;
    float *rs;
    cudaGetSymbolAddress((void**)&xqh, g_xqh); cudaGetSymbolAddress((void**)&xql, g_xql);
    cudaGetSymbolAddress((void**)&xkh, g_xkh); cudaGetSymbolAddress((void**)&xkl, g_xkl);
    cudaGetSymbolAddress((void**)&xvh, g_xvh); cudaGetSymbolAddress((void**)&xvl, g_xvl);
    cudaGetSymbolAddress((void**)&wqh, g_wqh); cudaGetSymbolAddress((void**)&wql, g_wql);
    cudaGetSymbolAddress((void**)&wkh, g_wkh); cudaGetSymbolAddress((void**)&wkl, g_wkl);
    cudaGetSymbolAddress((void**)&wvh, g_wvh); cudaGetSymbolAddress((void**)&wvl, g_wvl);
    cudaGetSymbolAddress((void**)&woh, g_woh); cudaGetSymbolAddress((void**)&wol, g_wol);
    cudaGetSymbolAddress((void**)&cxh, g_cxh); cudaGetSymbolAddress((void**)&cxl, g_cxl);
    cudaGetSymbolAddress((void**)&qh, g_qh);   cudaGetSymbolAddress((void**)&ql, g_ql);
    cudaGetSymbolAddress((void**)&kh, g_kh);   cudaGetSymbolAddress((void**)&kl, g_kl);
    cudaGetSymbolAddress((void**)&vh, g_vh);   cudaGetSymbolAddress((void**)&vl, g_vl);
    cudaGetSymbolAddress((void**)&rs, g_rs);

    const bool want_attn = ((long long)out_size >= OUT_ELEMS + ATT_ELEMS);
    float* attn = want_attn ? (out + OUT_ELEMS) : nullptr;

    // ---- 1. split fp32 inputs/weights into fp16 hi/lo planes ----
    ConvArgs ca{};
    ca.src[0] = query; ca.hi[0] = xqh; ca.lo[0] = xql; ca.n4[0] = (int)(OUT_ELEMS / 4);
    ca.src[1] = key_i; ca.hi[1] = xkh; ca.lo[1] = xkl; ca.n4[1] = (int)(OUT_ELEMS / 4);
    ca.src[2] = value; ca.hi[2] = xvh; ca.lo[2] = xvl; ca.n4[2] = (int)(OUT_ELEMS / 4);
    ca.src[3] = w_q;   ca.hi[3] = wqh; ca.lo[3] = wql; ca.n4[3] = D * D / 4;
    ca.src[4] = w_k;   ca.hi[4] = wkh; ca.lo[4] = wkl; ca.n4[4] = D * D / 4;
    ca.src[5] = w_v;   ca.hi[5] = wvh; ca.lo[5] = wvl; ca.n4[5] = D * D / 4;
    ca.src[6] = w_o;   ca.hi[6] = woh; ca.lo[6] = wol; ca.n4[6] = D * D / 4;
    convert_split<<<dim3((unsigned)(OUT_ELEMS / 4 / 256), 1, 7), 256>>>(ca);

    cudaFuncSetAttribute(gemm_hf<1>, cudaFuncAttributeMaxDynamicSharedMemorySize, GSMEM);
    cudaFuncSetAttribute(gemm_hf<0>, cudaFuncAttributeMaxDynamicSharedMemorySize, GSMEM);
    cudaFuncSetAttribute(pass1_vproj, cudaFuncAttributeMaxDynamicSharedMemorySize, ASMEM);
    cudaFuncSetAttribute(attn_pass2<true>, cudaFuncAttributeMaxDynamicSharedMemorySize, ASMEM);
    cudaFuncSetAttribute(attn_pass2<false>, cudaFuncAttributeMaxDynamicSharedMemorySize, ASMEM);

    GemmArgs gp{};
    gp.ah[0] = xqh; gp.al[0] = xql; gp.bh[0] = wqh; gp.bl[0] = wql;
    gp.ah[1] = xkh; gp.al[1] = xkl; gp.bh[1] = wkh; gp.bl[1] = wkl;
    gp.ah[2] = xvh; gp.al[2] = xvl; gp.bh[2] = wvh; gp.bl[2] = wvl;
    gp.chi[0] = qh; gp.clo[0] = ql;
    gp.chi[1] = kh; gp.clo[1] = kl;
    gp.chi[2] = vh; gp.clo[2] = vl;

    if (want_attn) {
        // ---- 2. Q,K projections ----
        gemm_hf<1><<<dim3(8, 32, 2), 256, GSMEM>>>(gp);
        // ---- 3. heterogeneous: V projection (256) + pass1 1-mma (1024) ----
        pass1_vproj<<<256 + 1024, 256, ASMEM>>>(qh, kh, rs,
                                                xvh, xvl, wvh, wvl, vh, vl);
        // ---- 4. pass 2 (2-term QK, K-hi only) ----
        attn_pass2<true><<<dim3(S / 64, BH), 256, ASMEM>>>(
            qh, ql, kh, vh, vl, rs, cxh, cxl, attn);
    } else {
        gemm_hf<1><<<dim3(8, 32, 3), 256, GSMEM>>>(gp);
        attn_pass2<false><<<dim3(S / 64, BH), 256, ASMEM>>>(
            qh, ql, kh, vh, vl, rs, cxh, cxl, nullptr);
    }

    // ---- 5. out = ctx @ Wo^T ----
    GemmArgs go{};
    go.ah[0] = cxh; go.al[0] = cxl; go.bh[0] = woh; go.bl[0] = wol;
    go.c = out;
    gemm_hf<0><<<dim3(8, 32, 1), 256, GSMEM>>>(go);
}